// round 5
// baseline (speedup 1.0000x reference)
#include <cuda_runtime.h>
#include <cuda_bf16.h>
#include <cstdint>
#include <cstddef>

#define NN   65536
#define NE   1048576
#define FIN  128
#define H1D  128
#define H2D  256
#define NC   16

// Scratch (device globals — no allocation allowed)
__device__ uint32_t g_ybf[(size_t)NN * H1D / 2];  // relu(x@Wp^T+bp), packed bf16x2
__device__ float    g_pooled[(size_t)NN * H1D];   // segment_max (fp32)
__device__ float    g_h[(size_t)NN * H1D];        // hidden 1
__device__ float    g_h2[(size_t)NN * H2D];       // hidden 2
__device__ int      g_deg[NN];                    // in-degree
__device__ int      g_off[NN + 1];                // CSR row offsets (by dst)
__device__ int      g_cur[NN];                    // scatter cursors
__device__ int      g_esrc[NE];                   // CSR column (src) indices

// ---------------------------------------------------------------------------
__global__ void zero_kernel(float4* __restrict__ p, int n4) {
    int i = blockIdx.x * blockDim.x + threadIdx.x;
    int stride = gridDim.x * blockDim.x;
    float4 z = make_float4(0.f, 0.f, 0.f, 0.f);
    for (; i < n4; i += stride) p[i] = z;
}

// ---------------------------------------------------------------------------
__global__ void hist_kernel(int* __restrict__ deg, const int* __restrict__ dst) {
    int e = blockIdx.x * blockDim.x + threadIdx.x;
    if (e < NE) atomicAdd(&deg[__ldg(dst + e)], 1);
}

// Single-block exclusive scan over NN=65536 ints (1024 threads x 64 elems each).
__global__ __launch_bounds__(1024)
void scan_kernel(const int* __restrict__ deg, int* __restrict__ off, int* __restrict__ cur) {
    __shared__ int s[1024];
    const int t = threadIdx.x;
    const int base = t * 64;
    int sum = 0;
    #pragma unroll 8
    for (int i = 0; i < 64; i++) sum += deg[base + i];
    s[t] = sum;
    __syncthreads();
    // Hillis-Steele inclusive scan
    for (int d = 1; d < 1024; d <<= 1) {
        int v = (t >= d) ? s[t - d] : 0;
        __syncthreads();
        s[t] += v;
        __syncthreads();
    }
    int run = s[t] - sum;     // exclusive base for this chunk
    #pragma unroll 8
    for (int i = 0; i < 64; i++) {
        off[base + i] = run;
        cur[base + i] = run;
        run += deg[base + i];
    }
    if (t == 1023) off[NN] = s[1023];
}

__global__ void scatter_kernel(int* __restrict__ cur, int* __restrict__ esrc,
                               const int* __restrict__ src, const int* __restrict__ dst) {
    int e = blockIdx.x * blockDim.x + threadIdx.x;
    if (e < NE) {
        int p = atomicAdd(&cur[__ldg(dst + e)], 1);
        esrc[p] = __ldg(src + e);
    }
}

// ---------------------------------------------------------------------------
__device__ __forceinline__ uint32_t bmax2(uint32_t a, uint32_t b) {
    __nv_bfloat162 r = __hmax2(*(__nv_bfloat162*)&a, *(__nv_bfloat162*)&b);
    return *(uint32_t*)&r;
}

// One warp per node: pooled[n] = max over in-edges of y_bf16[src], fp32 out.
// Empty nodes write 0 (== reference's isneginf->0 rewrite; relu output >= 0).
__global__ __launch_bounds__(256)
void pool_kernel(float* __restrict__ pooled, const uint32_t* __restrict__ yb,
                 const int* __restrict__ off, const int* __restrict__ esrc)
{
    const int n    = (blockIdx.x * blockDim.x + threadIdx.x) >> 5;
    const int lane = threadIdx.x & 31;
    const int beg = __ldg(off + n), end = __ldg(off + n + 1);

    uint32_t a0 = 0, a1 = 0, b0 = 0, b1 = 0;
    int e = beg;
    for (; e + 1 < end; e += 2) {
        int s0 = __ldg(esrc + e), s1 = __ldg(esrc + e + 1);
        const uint32_t* r0 = yb + (size_t)s0 * 64;
        const uint32_t* r1 = yb + (size_t)s1 * 64;
        uint32_t v00 = __ldg(r0 + lane), v01 = __ldg(r0 + 32 + lane);
        uint32_t v10 = __ldg(r1 + lane), v11 = __ldg(r1 + 32 + lane);
        a0 = bmax2(a0, v00); a1 = bmax2(a1, v01);
        b0 = bmax2(b0, v10); b1 = bmax2(b1, v11);
    }
    if (e < end) {
        const uint32_t* r0 = yb + (size_t)__ldg(esrc + e) * 64;
        a0 = bmax2(a0, __ldg(r0 + lane));
        a1 = bmax2(a1, __ldg(r0 + 32 + lane));
    }
    a0 = bmax2(a0, b0);
    a1 = bmax2(a1, b1);

    float2 f0 = __bfloat1622float2(*(__nv_bfloat162*)&a0);
    float2 f1 = __bfloat1622float2(*(__nv_bfloat162*)&a1);
    float* pr = pooled + (size_t)n * H1D;
    *(float2*)(pr + 2 * lane)      = f0;
    *(float2*)(pr + 64 + 2 * lane) = f1;
}

// ---------------------------------------------------------------------------
// ACT: 0 = none, 1 = relu, 2 = leaky(0.01)
template <int ACT>
__device__ __forceinline__ float apply_act(float v) {
    if (ACT == 1) return v > 0.f ? v : 0.f;
    if (ACT == 2) return v > 0.f ? v : 0.01f * v;
    return v;
}

__device__ __forceinline__ uint32_t f2tf32(float f) {
    uint32_t u;
    asm("cvt.rna.tf32.f32 %0, %1;" : "=r"(u) : "f"(f));
    return u;
}

__device__ __forceinline__ void mma8(float* d, const uint32_t* a, const uint32_t* b) {
    asm volatile(
        "mma.sync.aligned.m16n8k8.row.col.f32.tf32.tf32.f32 "
        "{%0,%1,%2,%3}, {%4,%5,%6,%7}, {%8,%9}, {%0,%1,%2,%3};\n"
        : "+f"(d[0]), "+f"(d[1]), "+f"(d[2]), "+f"(d[3])
        : "r"(a[0]), "r"(a[1]), "r"(a[2]), "r"(a[3]), "r"(b[0]), "r"(b[1]));
}

__device__ __forceinline__ void cp16(uint32_t s, const void* g) {
    asm volatile("cp.async.cg.shared.global [%0], [%1], 16;\n" :: "r"(s), "l"(g));
}

// ---------------------------------------------------------------------------
// C[M,N] = act( A1[M,128] @ B1[N,128]^T  (+ A2 @ B2^T if DUAL)  + bias )
// tf32 tensor-core GEMM: BM=128, BN=128, BK=32, 2-stage cp.async pipeline,
// 8 warps in 2x4 grid, warp tile 64x32, m16n8k8 fragments. Smem stride 36.
// OBF16: store output as packed bf16x2 instead of fp32.
#define GEMM_SMEM_BYTES (4 * 128 * 36 * 4)

template <int ACT, bool DUAL, bool OBF16>
__global__ __launch_bounds__(256, 2)
void mma_gemm(float* __restrict__ C,
              const float* __restrict__ A1, const float* __restrict__ B1,
              const float* __restrict__ A2, const float* __restrict__ B2,
              const float* __restrict__ bias, int N)
{
    constexpr int K = 128, BK = 32, LDSW = 36;
    constexpr int KT = DUAL ? 8 : 4;
    constexpr int BUF = 128 * LDSW;

    extern __shared__ float smem[];
    float* As[2] = { smem,         smem + BUF   };
    float* Bs[2] = { smem + 2*BUF, smem + 3*BUF };

    const int t    = threadIdx.x;
    const int lane = t & 31, w = t >> 5;
    const int wm = w >> 2, wn = w & 3;
    const int g  = lane >> 2, q = lane & 3;
    const int bm = blockIdx.y * 128, bn = blockIdx.x * 128;

    float acc[4][4][4];
    #pragma unroll
    for (int i = 0; i < 4; i++)
        #pragma unroll
        for (int j = 0; j < 4; j++)
            #pragma unroll
            for (int v = 0; v < 4; v++) acc[i][j][v] = 0.f;

    auto load_stage = [&](int kt, int st) {
        const float* Ap = (DUAL && kt >= 4) ? A2 : A1;
        const float* Bp = (DUAL && kt >= 4) ? B2 : B1;
        const int k0 = (kt & 3) * BK;
        #pragma unroll
        for (int i = 0; i < 4; i++) {
            int id  = t + i * 256;
            int row = id >> 3;
            int kv  = (id & 7) << 2;
            cp16((uint32_t)__cvta_generic_to_shared(&As[st][row * LDSW + kv]),
                 Ap + (size_t)(bm + row) * K + k0 + kv);
            cp16((uint32_t)__cvta_generic_to_shared(&Bs[st][row * LDSW + kv]),
                 Bp + (size_t)(bn + row) * K + k0 + kv);
        }
        asm volatile("cp.async.commit_group;\n");
    };

    load_stage(0, 0);

    #pragma unroll
    for (int kt = 0; kt < KT; kt++) {
        const int st = kt & 1;
        if (kt + 1 < KT) {
            load_stage(kt + 1, st ^ 1);
            asm volatile("cp.async.wait_group 1;\n");
        } else {
            asm volatile("cp.async.wait_group 0;\n");
        }
        __syncthreads();

        const float* Aw = &As[st][(wm * 64) * LDSW];
        const float* Bw = &Bs[st][(wn * 32) * LDSW];

        #pragma unroll
        for (int kk = 0; kk < 4; kk++) {
            const int kb = kk * 8;
            uint32_t bf[4][2];
            #pragma unroll
            for (int nj = 0; nj < 4; nj++) {
                bf[nj][0] = f2tf32(Bw[(nj * 8 + g) * LDSW + kb + q]);
                bf[nj][1] = f2tf32(Bw[(nj * 8 + g) * LDSW + kb + q + 4]);
            }
            #pragma unroll
            for (int mi = 0; mi < 4; mi++) {
                uint32_t af[4];
                af[0] = f2tf32(Aw[(mi * 16 + g    ) * LDSW + kb + q    ]);
                af[1] = f2tf32(Aw[(mi * 16 + g + 8) * LDSW + kb + q    ]);
                af[2] = f2tf32(Aw[(mi * 16 + g    ) * LDSW + kb + q + 4]);
                af[3] = f2tf32(Aw[(mi * 16 + g + 8) * LDSW + kb + q + 4]);
                #pragma unroll
                for (int nj = 0; nj < 4; nj++)
                    mma8(acc[mi][nj], af, bf[nj]);
            }
        }
        __syncthreads();
    }

    #pragma unroll
    for (int mi = 0; mi < 4; mi++) {
        const int r0 = bm + wm * 64 + mi * 16 + g;
        #pragma unroll
        for (int nj = 0; nj < 4; nj++) {
            const int c = bn + wn * 32 + nj * 8 + q * 2;
            const float bx = bias[c], by = bias[c + 1];
            float2 v0, v1;
            v0.x = apply_act<ACT>(acc[mi][nj][0] + bx);
            v0.y = apply_act<ACT>(acc[mi][nj][1] + by);
            v1.x = apply_act<ACT>(acc[mi][nj][2] + bx);
            v1.y = apply_act<ACT>(acc[mi][nj][3] + by);
            if (OBF16) {
                uint32_t* Cb = (uint32_t*)C;
                __nv_bfloat162 p0 = __float22bfloat162_rn(v0);
                __nv_bfloat162 p1 = __float22bfloat162_rn(v1);
                Cb[(size_t)r0 * (N / 2) + c / 2]       = *(uint32_t*)&p0;
                Cb[(size_t)(r0 + 8) * (N / 2) + c / 2] = *(uint32_t*)&p1;
            } else {
                *(float2*)&C[(size_t)r0 * N + c]       = v0;
                *(float2*)&C[(size_t)(r0 + 8) * N + c] = v1;
            }
        }
    }
}

// ---------------------------------------------------------------------------
// out[n, c] = sigmoid( h2[n, :] . W2[c, :] + b2[c] ),  N=16 classes, K=256
__global__ __launch_bounds__(256)
void head_kernel(float* __restrict__ out, const float* __restrict__ h2,
                 const float* __restrict__ W2, const float* __restrict__ b2)
{
    __shared__ float sW[H2D][NC];
    __shared__ float sh[16][H2D + 4];

    int t = threadIdx.x;
    #pragma unroll
    for (int i = 0; i < 16; i++) {
        int idx = t + i * 256;
        int c = idx >> 8, k = idx & 255;
        sW[k][c] = W2[idx];
    }
    int r0 = blockIdx.x * 16;
    #pragma unroll
    for (int i = 0; i < 4; i++) {
        int vid = t + i * 256;
        int row = vid >> 6;
        int kv  = (vid & 63) << 2;
        *(float4*)&sh[row][kv] = *(const float4*)(h2 + (size_t)(r0 + row) * H2D + kv);
    }
    __syncthreads();

    int row = t >> 4, col = t & 15;
    float s = 0.f;
    #pragma unroll 8
    for (int k = 0; k < H2D; k++)
        s = fmaf(sh[row][k], sW[k][col], s);
    s += b2[col];
    out[(size_t)(r0 + row) * NC + col] = 1.0f / (1.0f + expf(-s));
}

// ---------------------------------------------------------------------------
extern "C" void kernel_launch(void* const* d_in, const int* in_sizes, int n_in,
                              void* d_out, int out_size)
{
    const float* x  = (const float*)d_in[0];
    const float* Wp = (const float*)d_in[1];
    const float* bp = (const float*)d_in[2];
    const float* Ws = (const float*)d_in[3];
    const float* Wn = (const float*)d_in[4];
    const float* bn = (const float*)d_in[5];
    const float* W1 = (const float*)d_in[6];
    const float* b1 = (const float*)d_in[7];
    const float* W2 = (const float*)d_in[8];
    const float* b2 = (const float*)d_in[9];
    const int*  src = (const int*)d_in[10];
    const int*  dst = (const int*)d_in[11];
    float* out = (float*)d_out;

    uint32_t* ybf;  float *pooled, *h, *h2;
    int *deg, *off, *cur, *esrc;
    cudaGetSymbolAddress((void**)&ybf,    g_ybf);
    cudaGetSymbolAddress((void**)&pooled, g_pooled);
    cudaGetSymbolAddress((void**)&h,      g_h);
    cudaGetSymbolAddress((void**)&h2,     g_h2);
    cudaGetSymbolAddress((void**)&deg,    g_deg);
    cudaGetSymbolAddress((void**)&off,    g_off);
    cudaGetSymbolAddress((void**)&cur,    g_cur);
    cudaGetSymbolAddress((void**)&esrc,   g_esrc);

    cudaFuncSetAttribute(mma_gemm<1, false, true >, cudaFuncAttributeMaxDynamicSharedMemorySize, GEMM_SMEM_BYTES);
    cudaFuncSetAttribute(mma_gemm<2, true,  false>, cudaFuncAttributeMaxDynamicSharedMemorySize, GEMM_SMEM_BYTES);
    cudaFuncSetAttribute(mma_gemm<2, false, false>, cudaFuncAttributeMaxDynamicSharedMemorySize, GEMM_SMEM_BYTES);

    // --- CSR build (by dst) ---
    zero_kernel<<<64, 256>>>((float4*)deg, NN / 4);
    hist_kernel<<<NE / 256, 256>>>(deg, dst);
    scan_kernel<<<1, 1024>>>(deg, off, cur);
    scatter_kernel<<<NE / 256, 256>>>(cur, esrc, src, dst);

    // y = relu(x @ Wp^T + bp), packed bf16  [hoisted per-NODE, 16x fewer FLOPs]
    mma_gemm<1, false, true><<<dim3(1, NN / 128), 256, GEMM_SMEM_BYTES>>>(
        (float*)ybf, x, Wp, nullptr, nullptr, bp, H1D);

    // pooled = segment_max(y[src], dst)  — CSR gather-max, no atomics
    pool_kernel<<<NN * 32 / 256, 256>>>(pooled, ybf, off, esrc);

    // h = leaky( x @ Ws^T + pooled @ Wn^T + bn )  — fused dual-source GEMM
    mma_gemm<2, true, false><<<dim3(1, NN / 128), 256, GEMM_SMEM_BYTES>>>(
        h, x, Ws, pooled, Wn, bn, H1D);

    // h2 = leaky( h @ W1^T + b1 )
    mma_gemm<2, false, false><<<dim3(2, NN / 128), 256, GEMM_SMEM_BYTES>>>(
        h2, h, W1, nullptr, nullptr, b1, H2D);

    // out = sigmoid( h2 @ W2^T + b2 )
    head_kernel<<<NN / 16, 256>>>(out, h2, W2, b2);
}

// round 8
// speedup vs baseline: 1.6322x; 1.6322x over previous
#include <cuda_runtime.h>
#include <cuda_bf16.h>
#include <cstdint>
#include <cstddef>

#define NN   65536
#define NE   1048576
#define FIN  128
#define H1D  128
#define H2D  256
#define NC   16

// Scratch (device globals — no allocation allowed)
__device__ uint32_t g_ybf[(size_t)NN * H1D / 2];  // relu(x@Wp^T+bp), packed bf16x2
__device__ float    g_pooled[(size_t)NN * H1D];   // segment_max (fp32)
__device__ float    g_h[(size_t)NN * H1D];        // hidden 1
__device__ float    g_h2[(size_t)NN * H2D];       // hidden 2
__device__ int      g_deg[NN];                    // in-degree
__device__ int      g_off[NN + 1];                // CSR row offsets (by dst)
__device__ int      g_cur[NN];                    // scatter cursors
__device__ int      g_esrc[NE];                   // CSR column (src) indices
__device__ int      g_chunk[256];                 // scan chunk sums / bases

// ---------------------------------------------------------------------------
__global__ void zero_kernel(float4* __restrict__ p, int n4) {
    int i = blockIdx.x * blockDim.x + threadIdx.x;
    int stride = gridDim.x * blockDim.x;
    float4 z = make_float4(0.f, 0.f, 0.f, 0.f);
    for (; i < n4; i += stride) p[i] = z;
}

// ---------------------------------------------------------------------------
// Histogram of dst (4 edges per thread, vectorized load)
__global__ void hist_kernel(int* __restrict__ deg, const int* __restrict__ dst) {
    int i = blockIdx.x * blockDim.x + threadIdx.x;   // < NE/4
    int4 d = __ldg((const int4*)dst + i);
    atomicAdd(&deg[d.x], 1);
    atomicAdd(&deg[d.y], 1);
    atomicAdd(&deg[d.z], 1);
    atomicAdd(&deg[d.w], 1);
}

// --- hierarchical exclusive scan over NN = 256*256 ---
// Phase A: per-chunk sums (256 blocks x 256 threads)
__global__ __launch_bounds__(256)
void scan_a(const int* __restrict__ deg, int* __restrict__ chunk) {
    __shared__ int s[256];
    int t = threadIdx.x, c = blockIdx.x;
    s[t] = deg[c * 256 + t];
    __syncthreads();
    for (int d = 128; d > 0; d >>= 1) {
        if (t < d) s[t] += s[t + d];
        __syncthreads();
    }
    if (t == 0) chunk[c] = s[0];
}

// Phase B: single-block exclusive scan of 256 chunk sums; writes off[NN]
__global__ __launch_bounds__(256)
void scan_b(int* __restrict__ chunk, int* __restrict__ off) {
    __shared__ int s[256];
    int t = threadIdx.x;
    int v = chunk[t];
    s[t] = v;
    __syncthreads();
    for (int d = 1; d < 256; d <<= 1) {
        int u = (t >= d) ? s[t - d] : 0;
        __syncthreads();
        s[t] += u;
        __syncthreads();
    }
    chunk[t] = s[t] - v;            // exclusive base per chunk
    if (t == 255) off[NN] = s[255]; // total == NE
}

// Phase C: per-chunk local exclusive scan + chunk base -> off, cur
__global__ __launch_bounds__(256)
void scan_c(const int* __restrict__ deg, const int* __restrict__ chunk,
            int* __restrict__ off, int* __restrict__ cur) {
    __shared__ int s[256];
    int t = threadIdx.x, c = blockIdx.x;
    int v = deg[c * 256 + t];
    s[t] = v;
    __syncthreads();
    for (int d = 1; d < 256; d <<= 1) {
        int u = (t >= d) ? s[t - d] : 0;
        __syncthreads();
        s[t] += u;
        __syncthreads();
    }
    int o = chunk[c] + s[t] - v;
    off[c * 256 + t] = o;
    cur[c * 256 + t] = o;
}

// Scatter src into CSR slots (4 edges per thread)
__global__ void scatter_kernel(int* __restrict__ cur, int* __restrict__ esrc,
                               const int* __restrict__ src, const int* __restrict__ dst) {
    int i = blockIdx.x * blockDim.x + threadIdx.x;   // < NE/4
    int4 d = __ldg((const int4*)dst + i);
    int4 s = __ldg((const int4*)src + i);
    esrc[atomicAdd(&cur[d.x], 1)] = s.x;
    esrc[atomicAdd(&cur[d.y], 1)] = s.y;
    esrc[atomicAdd(&cur[d.z], 1)] = s.z;
    esrc[atomicAdd(&cur[d.w], 1)] = s.w;
}

// ---------------------------------------------------------------------------
__device__ __forceinline__ uint32_t bmax2(uint32_t a, uint32_t b) {
    __nv_bfloat162 r = __hmax2(*(__nv_bfloat162*)&a, *(__nv_bfloat162*)&b);
    return *(uint32_t*)&r;
}

// One warp per node: pooled[n] = max over in-edges of y_bf16[src], fp32 out.
// Unrolled x4 with independent accumulators: 8 concurrent 128B loads per warp
// (MLP=8) to hide L2 latency. Empty nodes write 0 (== isneginf->0 rewrite).
__global__ __launch_bounds__(256)
void pool_kernel(float* __restrict__ pooled, const uint32_t* __restrict__ yb,
                 const int* __restrict__ off, const int* __restrict__ esrc)
{
    const int n    = (blockIdx.x * blockDim.x + threadIdx.x) >> 5;
    const int lane = threadIdx.x & 31;
    const int beg = __ldg(off + n), end = __ldg(off + n + 1);

    uint32_t a[4][2] = {};
    int e = beg;
    const int end4 = beg + ((end - beg) & ~3);
    #pragma unroll 1
    for (; e < end4; e += 4) {
        int s0 = __ldg(esrc + e);
        int s1 = __ldg(esrc + e + 1);
        int s2 = __ldg(esrc + e + 2);
        int s3 = __ldg(esrc + e + 3);
        const uint32_t* r0 = yb + (size_t)s0 * 64;
        const uint32_t* r1 = yb + (size_t)s1 * 64;
        const uint32_t* r2 = yb + (size_t)s2 * 64;
        const uint32_t* r3 = yb + (size_t)s3 * 64;
        uint32_t v00 = __ldg(r0 + lane), v01 = __ldg(r0 + 32 + lane);
        uint32_t v10 = __ldg(r1 + lane), v11 = __ldg(r1 + 32 + lane);
        uint32_t v20 = __ldg(r2 + lane), v21 = __ldg(r2 + 32 + lane);
        uint32_t v30 = __ldg(r3 + lane), v31 = __ldg(r3 + 32 + lane);
        a[0][0] = bmax2(a[0][0], v00); a[0][1] = bmax2(a[0][1], v01);
        a[1][0] = bmax2(a[1][0], v10); a[1][1] = bmax2(a[1][1], v11);
        a[2][0] = bmax2(a[2][0], v20); a[2][1] = bmax2(a[2][1], v21);
        a[3][0] = bmax2(a[3][0], v30); a[3][1] = bmax2(a[3][1], v31);
    }
    #pragma unroll 1
    for (; e < end; e++) {
        const uint32_t* r0 = yb + (size_t)__ldg(esrc + e) * 64;
        a[0][0] = bmax2(a[0][0], __ldg(r0 + lane));
        a[0][1] = bmax2(a[0][1], __ldg(r0 + 32 + lane));
    }
    a[0][0] = bmax2(bmax2(a[0][0], a[1][0]), bmax2(a[2][0], a[3][0]));
    a[0][1] = bmax2(bmax2(a[0][1], a[1][1]), bmax2(a[2][1], a[3][1]));

    float2 f0 = __bfloat1622float2(*(__nv_bfloat162*)&a[0][0]);
    float2 f1 = __bfloat1622float2(*(__nv_bfloat162*)&a[0][1]);
    float* pr = pooled + (size_t)n * H1D;
    *(float2*)(pr + 2 * lane)      = f0;
    *(float2*)(pr + 64 + 2 * lane) = f1;
}

// ---------------------------------------------------------------------------
// ACT: 0 = none, 1 = relu, 2 = leaky(0.01)
template <int ACT>
__device__ __forceinline__ float apply_act(float v) {
    if (ACT == 1) return v > 0.f ? v : 0.f;
    if (ACT == 2) return v > 0.f ? v : 0.01f * v;
    return v;
}

__device__ __forceinline__ uint32_t f2tf32(float f) {
    uint32_t u;
    asm("cvt.rna.tf32.f32 %0, %1;" : "=r"(u) : "f"(f));
    return u;
}

__device__ __forceinline__ void mma8(float* d, const uint32_t* a, const uint32_t* b) {
    asm volatile(
        "mma.sync.aligned.m16n8k8.row.col.f32.tf32.tf32.f32 "
        "{%0,%1,%2,%3}, {%4,%5,%6,%7}, {%8,%9}, {%0,%1,%2,%3};\n"
        : "+f"(d[0]), "+f"(d[1]), "+f"(d[2]), "+f"(d[3])
        : "r"(a[0]), "r"(a[1]), "r"(a[2]), "r"(a[3]), "r"(b[0]), "r"(b[1]));
}

__device__ __forceinline__ void cp16(uint32_t s, const void* g) {
    asm volatile("cp.async.cg.shared.global [%0], [%1], 16;\n" :: "r"(s), "l"(g));
}

// ---------------------------------------------------------------------------
// C[M,N] = act( A1[M,128] @ B1[N,128]^T  (+ A2 @ B2^T if DUAL)  + bias )
// tf32 tensor-core GEMM: BM=128, BN=128, BK=32, 2-stage cp.async pipeline,
// 8 warps in 2x4 grid, warp tile 64x32, m16n8k8 fragments. Smem stride 36.
// OBF16: store output as packed bf16x2 instead of fp32.
#define GEMM_SMEM_BYTES (4 * 128 * 36 * 4)

template <int ACT, bool DUAL, bool OBF16>
__global__ __launch_bounds__(256, 2)
void mma_gemm(float* __restrict__ C,
              const float* __restrict__ A1, const float* __restrict__ B1,
              const float* __restrict__ A2, const float* __restrict__ B2,
              const float* __restrict__ bias, int N)
{
    constexpr int K = 128, BK = 32, LDSW = 36;
    constexpr int KT = DUAL ? 8 : 4;
    constexpr int BUF = 128 * LDSW;

    extern __shared__ float smem[];
    float* As[2] = { smem,         smem + BUF   };
    float* Bs[2] = { smem + 2*BUF, smem + 3*BUF };

    const int t    = threadIdx.x;
    const int lane = t & 31, w = t >> 5;
    const int wm = w >> 2, wn = w & 3;
    const int g  = lane >> 2, q = lane & 3;
    const int bm = blockIdx.y * 128, bn = blockIdx.x * 128;

    float acc[4][4][4];
    #pragma unroll
    for (int i = 0; i < 4; i++)
        #pragma unroll
        for (int j = 0; j < 4; j++)
            #pragma unroll
            for (int v = 0; v < 4; v++) acc[i][j][v] = 0.f;

    auto load_stage = [&](int kt, int st) {
        const float* Ap = (DUAL && kt >= 4) ? A2 : A1;
        const float* Bp = (DUAL && kt >= 4) ? B2 : B1;
        const int k0 = (kt & 3) * BK;
        #pragma unroll
        for (int i = 0; i < 4; i++) {
            int id  = t + i * 256;
            int row = id >> 3;
            int kv  = (id & 7) << 2;
            cp16((uint32_t)__cvta_generic_to_shared(&As[st][row * LDSW + kv]),
                 Ap + (size_t)(bm + row) * K + k0 + kv);
            cp16((uint32_t)__cvta_generic_to_shared(&Bs[st][row * LDSW + kv]),
                 Bp + (size_t)(bn + row) * K + k0 + kv);
        }
        asm volatile("cp.async.commit_group;\n");
    };

    load_stage(0, 0);

    #pragma unroll
    for (int kt = 0; kt < KT; kt++) {
        const int st = kt & 1;
        if (kt + 1 < KT) {
            load_stage(kt + 1, st ^ 1);
            asm volatile("cp.async.wait_group 1;\n");
        } else {
            asm volatile("cp.async.wait_group 0;\n");
        }
        __syncthreads();

        const float* Aw = &As[st][(wm * 64) * LDSW];
        const float* Bw = &Bs[st][(wn * 32) * LDSW];

        #pragma unroll
        for (int kk = 0; kk < 4; kk++) {
            const int kb = kk * 8;
            uint32_t bf[4][2];
            #pragma unroll
            for (int nj = 0; nj < 4; nj++) {
                bf[nj][0] = f2tf32(Bw[(nj * 8 + g) * LDSW + kb + q]);
                bf[nj][1] = f2tf32(Bw[(nj * 8 + g) * LDSW + kb + q + 4]);
            }
            #pragma unroll
            for (int mi = 0; mi < 4; mi++) {
                uint32_t af[4];
                af[0] = f2tf32(Aw[(mi * 16 + g    ) * LDSW + kb + q    ]);
                af[1] = f2tf32(Aw[(mi * 16 + g + 8) * LDSW + kb + q    ]);
                af[2] = f2tf32(Aw[(mi * 16 + g    ) * LDSW + kb + q + 4]);
                af[3] = f2tf32(Aw[(mi * 16 + g + 8) * LDSW + kb + q + 4]);
                #pragma unroll
                for (int nj = 0; nj < 4; nj++)
                    mma8(acc[mi][nj], af, bf[nj]);
            }
        }
        __syncthreads();
    }

    #pragma unroll
    for (int mi = 0; mi < 4; mi++) {
        const int r0 = bm + wm * 64 + mi * 16 + g;
        #pragma unroll
        for (int nj = 0; nj < 4; nj++) {
            const int c = bn + wn * 32 + nj * 8 + q * 2;
            const float bx = bias[c], by = bias[c + 1];
            float2 v0, v1;
            v0.x = apply_act<ACT>(acc[mi][nj][0] + bx);
            v0.y = apply_act<ACT>(acc[mi][nj][1] + by);
            v1.x = apply_act<ACT>(acc[mi][nj][2] + bx);
            v1.y = apply_act<ACT>(acc[mi][nj][3] + by);
            if (OBF16) {
                uint32_t* Cb = (uint32_t*)C;
                __nv_bfloat162 p0 = __float22bfloat162_rn(v0);
                __nv_bfloat162 p1 = __float22bfloat162_rn(v1);
                Cb[(size_t)r0 * (N / 2) + c / 2]       = *(uint32_t*)&p0;
                Cb[(size_t)(r0 + 8) * (N / 2) + c / 2] = *(uint32_t*)&p1;
            } else {
                *(float2*)&C[(size_t)r0 * N + c]       = v0;
                *(float2*)&C[(size_t)(r0 + 8) * N + c] = v1;
            }
        }
    }
}

// ---------------------------------------------------------------------------
// out[n, c] = sigmoid( h2[n, :] . W2[c, :] + b2[c] ),  N=16 classes, K=256
__global__ __launch_bounds__(256)
void head_kernel(float* __restrict__ out, const float* __restrict__ h2,
                 const float* __restrict__ W2, const float* __restrict__ b2)
{
    __shared__ float sW[H2D][NC];
    __shared__ float sh[16][H2D + 4];

    int t = threadIdx.x;
    #pragma unroll
    for (int i = 0; i < 16; i++) {
        int idx = t + i * 256;
        int c = idx >> 8, k = idx & 255;
        sW[k][c] = W2[idx];
    }
    int r0 = blockIdx.x * 16;
    #pragma unroll
    for (int i = 0; i < 4; i++) {
        int vid = t + i * 256;
        int row = vid >> 6;
        int kv  = (vid & 63) << 2;
        *(float4*)&sh[row][kv] = *(const float4*)(h2 + (size_t)(r0 + row) * H2D + kv);
    }
    __syncthreads();

    int row = t >> 4, col = t & 15;
    float s = 0.f;
    #pragma unroll 8
    for (int k = 0; k < H2D; k++)
        s = fmaf(sh[row][k], sW[k][col], s);
    s += b2[col];
    out[(size_t)(r0 + row) * NC + col] = 1.0f / (1.0f + expf(-s));
}

// ---------------------------------------------------------------------------
extern "C" void kernel_launch(void* const* d_in, const int* in_sizes, int n_in,
                              void* d_out, int out_size)
{
    const float* x  = (const float*)d_in[0];
    const float* Wp = (const float*)d_in[1];
    const float* bp = (const float*)d_in[2];
    const float* Ws = (const float*)d_in[3];
    const float* Wn = (const float*)d_in[4];
    const float* bn = (const float*)d_in[5];
    const float* W1 = (const float*)d_in[6];
    const float* b1 = (const float*)d_in[7];
    const float* W2 = (const float*)d_in[8];
    const float* b2 = (const float*)d_in[9];
    const int*  src = (const int*)d_in[10];
    const int*  dst = (const int*)d_in[11];
    float* out = (float*)d_out;

    uint32_t* ybf;  float *pooled, *h, *h2;
    int *deg, *off, *cur, *esrc, *chunk;
    cudaGetSymbolAddress((void**)&ybf,    g_ybf);
    cudaGetSymbolAddress((void**)&pooled, g_pooled);
    cudaGetSymbolAddress((void**)&h,      g_h);
    cudaGetSymbolAddress((void**)&h2,     g_h2);
    cudaGetSymbolAddress((void**)&deg,    g_deg);
    cudaGetSymbolAddress((void**)&off,    g_off);
    cudaGetSymbolAddress((void**)&cur,    g_cur);
    cudaGetSymbolAddress((void**)&esrc,   g_esrc);
    cudaGetSymbolAddress((void**)&chunk,  g_chunk);

    cudaFuncSetAttribute(mma_gemm<1, false, true >, cudaFuncAttributeMaxDynamicSharedMemorySize, GEMM_SMEM_BYTES);
    cudaFuncSetAttribute(mma_gemm<2, true,  false>, cudaFuncAttributeMaxDynamicSharedMemorySize, GEMM_SMEM_BYTES);
    cudaFuncSetAttribute(mma_gemm<2, false, false>, cudaFuncAttributeMaxDynamicSharedMemorySize, GEMM_SMEM_BYTES);

    // --- CSR build (by dst) ---
    zero_kernel<<<64, 256>>>((float4*)deg, NN / 4);
    hist_kernel<<<NE / 1024, 256>>>(deg, dst);
    scan_a<<<256, 256>>>(deg, chunk);
    scan_b<<<1, 256>>>(chunk, off);
    scan_c<<<256, 256>>>(deg, chunk, off, cur);
    scatter_kernel<<<NE / 1024, 256>>>(cur, esrc, src, dst);

    // y = relu(x @ Wp^T + bp), packed bf16  [hoisted per-NODE, 16x fewer FLOPs]
    mma_gemm<1, false, true><<<dim3(1, NN / 128), 256, GEMM_SMEM_BYTES>>>(
        (float*)ybf, x, Wp, nullptr, nullptr, bp, H1D);

    // pooled = segment_max(y[src], dst)  — CSR gather-max, no atomics
    pool_kernel<<<NN * 32 / 256, 256>>>(pooled, ybf, off, esrc);

    // h = leaky( x @ Ws^T + pooled @ Wn^T + bn )  — fused dual-source GEMM
    mma_gemm<2, true, false><<<dim3(1, NN / 128), 256, GEMM_SMEM_BYTES>>>(
        h, x, Ws, pooled, Wn, bn, H1D);

    // h2 = leaky( h @ W1^T + b1 )
    mma_gemm<2, false, false><<<dim3(2, NN / 128), 256, GEMM_SMEM_BYTES>>>(
        h2, h, W1, nullptr, nullptr, b1, H2D);

    // out = sigmoid( h2 @ W2^T + b2 )
    head_kernel<<<NN / 16, 256>>>(out, h2, W2, b2);
}

// round 10
// speedup vs baseline: 1.6869x; 1.0335x over previous
#include <cuda_runtime.h>
#include <cuda_bf16.h>
#include <cstdint>
#include <cstddef>

#define NN   65536
#define NE   1048576
#define FIN  128
#define H1D  128
#define H2D  256
#define NC   16

// Scratch (device globals — no allocation allowed)
__device__ uint32_t g_ybf[(size_t)NN * H1D / 2];  // relu(x@Wp^T+bp), packed bf16x2
__device__ float    g_pooled[(size_t)NN * H1D];   // segment_max (fp32)
__device__ float    g_h[(size_t)NN * H1D];        // hidden 1
__device__ float    g_h2[(size_t)NN * H2D];       // hidden 2
__device__ int      g_deg[NN];                    // in-degree
__device__ int      g_off[NN + 1];                // CSR row offsets (by dst)
__device__ int      g_cur[NN];                    // scatter cursors
__device__ int      g_esrc[NE];                   // CSR column (src) indices
__device__ int      g_chunk[256];                 // scan chunk sums / bases

// ---------------------------------------------------------------------------
__global__ void zero_kernel(float4* __restrict__ p, int n4) {
    int i = blockIdx.x * blockDim.x + threadIdx.x;
    int stride = gridDim.x * blockDim.x;
    float4 z = make_float4(0.f, 0.f, 0.f, 0.f);
    for (; i < n4; i += stride) p[i] = z;
}

// ---------------------------------------------------------------------------
// Histogram of dst (4 edges per thread, vectorized load)
__global__ void hist_kernel(int* __restrict__ deg, const int* __restrict__ dst) {
    int i = blockIdx.x * blockDim.x + threadIdx.x;   // < NE/4
    int4 d = __ldg((const int4*)dst + i);
    atomicAdd(&deg[d.x], 1);
    atomicAdd(&deg[d.y], 1);
    atomicAdd(&deg[d.z], 1);
    atomicAdd(&deg[d.w], 1);
}

// --- hierarchical exclusive scan over NN = 256*256 ---
__global__ __launch_bounds__(256)
void scan_a(const int* __restrict__ deg, int* __restrict__ chunk) {
    __shared__ int s[256];
    int t = threadIdx.x, c = blockIdx.x;
    s[t] = deg[c * 256 + t];
    __syncthreads();
    for (int d = 128; d > 0; d >>= 1) {
        if (t < d) s[t] += s[t + d];
        __syncthreads();
    }
    if (t == 0) chunk[c] = s[0];
}

__global__ __launch_bounds__(256)
void scan_b(int* __restrict__ chunk, int* __restrict__ off) {
    __shared__ int s[256];
    int t = threadIdx.x;
    int v = chunk[t];
    s[t] = v;
    __syncthreads();
    for (int d = 1; d < 256; d <<= 1) {
        int u = (t >= d) ? s[t - d] : 0;
        __syncthreads();
        s[t] += u;
        __syncthreads();
    }
    chunk[t] = s[t] - v;
    if (t == 255) off[NN] = s[255];
}

__global__ __launch_bounds__(256)
void scan_c(const int* __restrict__ deg, const int* __restrict__ chunk,
            int* __restrict__ off, int* __restrict__ cur) {
    __shared__ int s[256];
    int t = threadIdx.x, c = blockIdx.x;
    int v = deg[c * 256 + t];
    s[t] = v;
    __syncthreads();
    for (int d = 1; d < 256; d <<= 1) {
        int u = (t >= d) ? s[t - d] : 0;
        __syncthreads();
        s[t] += u;
        __syncthreads();
    }
    int o = chunk[c] + s[t] - v;
    off[c * 256 + t] = o;
    cur[c * 256 + t] = o;
}

__global__ void scatter_kernel(int* __restrict__ cur, int* __restrict__ esrc,
                               const int* __restrict__ src, const int* __restrict__ dst) {
    int i = blockIdx.x * blockDim.x + threadIdx.x;   // < NE/4
    int4 d = __ldg((const int4*)dst + i);
    int4 s = __ldg((const int4*)src + i);
    esrc[atomicAdd(&cur[d.x], 1)] = s.x;
    esrc[atomicAdd(&cur[d.y], 1)] = s.y;
    esrc[atomicAdd(&cur[d.z], 1)] = s.z;
    esrc[atomicAdd(&cur[d.w], 1)] = s.w;
}

// ---------------------------------------------------------------------------
__device__ __forceinline__ uint32_t bmax2(uint32_t a, uint32_t b) {
    __nv_bfloat162 r = __hmax2(*(__nv_bfloat162*)&a, *(__nv_bfloat162*)&b);
    return *(uint32_t*)&r;
}
__device__ __forceinline__ uint4 bmax4(uint4 a, uint4 b) {
    uint4 r;
    r.x = bmax2(a.x, b.x); r.y = bmax2(a.y, b.y);
    r.z = bmax2(a.z, b.z); r.w = bmax2(a.w, b.w);
    return r;
}

// One warp per node: pooled[n] = max over in-edges of y_bf16[src], fp32 out.
// 16 lanes per 256B row (uint4 loads): half-warp 0 takes even edges, half 1
// odd edges; 2 independent LDG.128 per lane in flight; cross-half combine via
// shfl_xor(16). Empty nodes write 0 (== reference's isneginf->0 rewrite).
__global__ __launch_bounds__(256)
void pool_kernel(float* __restrict__ pooled, const uint4* __restrict__ yb4,
                 const int* __restrict__ off, const int* __restrict__ esrc)
{
    const int n    = (blockIdx.x * blockDim.x + threadIdx.x) >> 5;
    const int lane = threadIdx.x & 31;
    const int half = lane >> 4, sl = lane & 15;
    const int beg = __ldg(off + n), end = __ldg(off + n + 1);

    uint4 a0 = {0u, 0u, 0u, 0u}, a1 = {0u, 0u, 0u, 0u};
    int e = beg;
    #pragma unroll 1
    for (; e + 3 < end; e += 4) {          // 4 edges: 2 per half-warp
        int s0 = __ldg(esrc + e + half);
        int s1 = __ldg(esrc + e + 2 + half);
        uint4 v0 = __ldg(yb4 + (size_t)s0 * 16 + sl);
        uint4 v1 = __ldg(yb4 + (size_t)s1 * 16 + sl);
        a0 = bmax4(a0, v0);
        a1 = bmax4(a1, v1);
    }
    if (e + 1 < end) {                     // 2 edges (one per half)
        int s0 = __ldg(esrc + e + half);
        a0 = bmax4(a0, __ldg(yb4 + (size_t)s0 * 16 + sl));
        e += 2;
    }
    if (e < end) {                         // last edge (both halves load it)
        int s0 = __ldg(esrc + e);
        a0 = bmax4(a0, __ldg(yb4 + (size_t)s0 * 16 + sl));
    }
    a0 = bmax4(a0, a1);
    // combine across half-warps (max is order-invariant)
    a0.x = bmax2(a0.x, __shfl_xor_sync(0xFFFFFFFFu, a0.x, 16));
    a0.y = bmax2(a0.y, __shfl_xor_sync(0xFFFFFFFFu, a0.y, 16));
    a0.z = bmax2(a0.z, __shfl_xor_sync(0xFFFFFFFFu, a0.z, 16));
    a0.w = bmax2(a0.w, __shfl_xor_sync(0xFFFFFFFFu, a0.w, 16));

    // lane sl holds bf16 cols [8sl, 8sl+8): half0 writes cols 8sl..+3 (x,y),
    // half1 writes cols 8sl+4..+7 (z,w). Warp covers the full 512B fp32 row.
    uint32_t lo = half ? a0.z : a0.x;
    uint32_t hi = half ? a0.w : a0.y;
    float2 f0 = __bfloat1622float2(*(__nv_bfloat162*)&lo);
    float2 f1 = __bfloat1622float2(*(__nv_bfloat162*)&hi);
    float4 v = make_float4(f0.x, f0.y, f1.x, f1.y);
    *(float4*)(pooled + (size_t)n * H1D + 8 * sl + 4 * half) = v;
}

// ---------------------------------------------------------------------------
// ACT: 0 = none, 1 = relu, 2 = leaky(0.01)
template <int ACT>
__device__ __forceinline__ float apply_act(float v) {
    if (ACT == 1) return v > 0.f ? v : 0.f;
    if (ACT == 2) return v > 0.f ? v : 0.01f * v;
    return v;
}

// Raw fp32 bits as tf32 operand: HMMA.TF32 reads only the top 19 bits, so the
// explicit cvt.rna.tf32 round is unnecessary (truncation; CUTLASS fast-tf32).
// Removes ~384 ALU cvt ops per thread per GEMM pass that competed for issue.
__device__ __forceinline__ uint32_t f2tf32(float f) { return __float_as_uint(f); }

__device__ __forceinline__ void mma8(float* d, const uint32_t* a, const uint32_t* b) {
    asm volatile(
        "mma.sync.aligned.m16n8k8.row.col.f32.tf32.tf32.f32 "
        "{%0,%1,%2,%3}, {%4,%5,%6,%7}, {%8,%9}, {%0,%1,%2,%3};\n"
        : "+f"(d[0]), "+f"(d[1]), "+f"(d[2]), "+f"(d[3])
        : "r"(a[0]), "r"(a[1]), "r"(a[2]), "r"(a[3]), "r"(b[0]), "r"(b[1]));
}

__device__ __forceinline__ void cp16(uint32_t s, const void* g) {
    asm volatile("cp.async.cg.shared.global [%0], [%1], 16;\n" :: "r"(s), "l"(g));
}

// ---------------------------------------------------------------------------
// C[M,N] = act( A1[M,128] @ B1[N,128]^T  (+ A2 @ B2^T if DUAL)  + bias )
// tf32 tensor-core GEMM: BM=128, BN=128, BK=32, 2-stage cp.async pipeline,
// 8 warps in 2x4 grid, warp tile 64x32, m16n8k8 fragments. Smem stride 36.
// OBF16: store output as packed bf16x2 instead of fp32.
#define GEMM_SMEM_BYTES (4 * 128 * 36 * 4)

template <int ACT, bool DUAL, bool OBF16>
__global__ __launch_bounds__(256, 2)
void mma_gemm(float* __restrict__ C,
              const float* __restrict__ A1, const float* __restrict__ B1,
              const float* __restrict__ A2, const float* __restrict__ B2,
              const float* __restrict__ bias, int N)
{
    constexpr int K = 128, BK = 32, LDSW = 36;
    constexpr int KT = DUAL ? 8 : 4;
    constexpr int BUF = 128 * LDSW;

    extern __shared__ float smem[];
    float* As[2] = { smem,         smem + BUF   };
    float* Bs[2] = { smem + 2*BUF, smem + 3*BUF };

    const int t    = threadIdx.x;
    const int lane = t & 31, w = t >> 5;
    const int wm = w >> 2, wn = w & 3;
    const int g  = lane >> 2, q = lane & 3;
    const int bm = blockIdx.y * 128, bn = blockIdx.x * 128;

    float acc[4][4][4];
    #pragma unroll
    for (int i = 0; i < 4; i++)
        #pragma unroll
        for (int j = 0; j < 4; j++)
            #pragma unroll
            for (int v = 0; v < 4; v++) acc[i][j][v] = 0.f;

    auto load_stage = [&](int kt, int st) {
        const float* Ap = (DUAL && kt >= 4) ? A2 : A1;
        const float* Bp = (DUAL && kt >= 4) ? B2 : B1;
        const int k0 = (kt & 3) * BK;
        #pragma unroll
        for (int i = 0; i < 4; i++) {
            int id  = t + i * 256;
            int row = id >> 3;
            int kv  = (id & 7) << 2;
            cp16((uint32_t)__cvta_generic_to_shared(&As[st][row * LDSW + kv]),
                 Ap + (size_t)(bm + row) * K + k0 + kv);
            cp16((uint32_t)__cvta_generic_to_shared(&Bs[st][row * LDSW + kv]),
                 Bp + (size_t)(bn + row) * K + k0 + kv);
        }
        asm volatile("cp.async.commit_group;\n");
    };

    load_stage(0, 0);

    #pragma unroll
    for (int kt = 0; kt < KT; kt++) {
        const int st = kt & 1;
        if (kt + 1 < KT) {
            load_stage(kt + 1, st ^ 1);
            asm volatile("cp.async.wait_group 1;\n");
        } else {
            asm volatile("cp.async.wait_group 0;\n");
        }
        __syncthreads();

        const float* Aw = &As[st][(wm * 64) * LDSW];
        const float* Bw = &Bs[st][(wn * 32) * LDSW];

        #pragma unroll
        for (int kk = 0; kk < 4; kk++) {
            const int kb = kk * 8;
            uint32_t bf[4][2];
            #pragma unroll
            for (int nj = 0; nj < 4; nj++) {
                bf[nj][0] = f2tf32(Bw[(nj * 8 + g) * LDSW + kb + q]);
                bf[nj][1] = f2tf32(Bw[(nj * 8 + g) * LDSW + kb + q + 4]);
            }
            #pragma unroll
            for (int mi = 0; mi < 4; mi++) {
                uint32_t af[4];
                af[0] = f2tf32(Aw[(mi * 16 + g    ) * LDSW + kb + q    ]);
                af[1] = f2tf32(Aw[(mi * 16 + g + 8) * LDSW + kb + q    ]);
                af[2] = f2tf32(Aw[(mi * 16 + g    ) * LDSW + kb + q + 4]);
                af[3] = f2tf32(Aw[(mi * 16 + g + 8) * LDSW + kb + q + 4]);
                #pragma unroll
                for (int nj = 0; nj < 4; nj++)
                    mma8(acc[mi][nj], af, bf[nj]);
            }
        }
        __syncthreads();
    }

    #pragma unroll
    for (int mi = 0; mi < 4; mi++) {
        const int r0 = bm + wm * 64 + mi * 16 + g;
        #pragma unroll
        for (int nj = 0; nj < 4; nj++) {
            const int c = bn + wn * 32 + nj * 8 + q * 2;
            const float bx = bias[c], by = bias[c + 1];
            float2 v0, v1;
            v0.x = apply_act<ACT>(acc[mi][nj][0] + bx);
            v0.y = apply_act<ACT>(acc[mi][nj][1] + by);
            v1.x = apply_act<ACT>(acc[mi][nj][2] + bx);
            v1.y = apply_act<ACT>(acc[mi][nj][3] + by);
            if (OBF16) {
                uint32_t* Cb = (uint32_t*)C;
                __nv_bfloat162 p0 = __float22bfloat162_rn(v0);
                __nv_bfloat162 p1 = __float22bfloat162_rn(v1);
                Cb[(size_t)r0 * (N / 2) + c / 2]       = *(uint32_t*)&p0;
                Cb[(size_t)(r0 + 8) * (N / 2) + c / 2] = *(uint32_t*)&p1;
            } else {
                *(float2*)&C[(size_t)r0 * N + c]       = v0;
                *(float2*)&C[(size_t)(r0 + 8) * N + c] = v1;
            }
        }
    }
}

// ---------------------------------------------------------------------------
// out[n, c] = sigmoid( h2[n, :] . W2[c, :] + b2[c] ),  N=16 classes, K=256
__global__ __launch_bounds__(256)
void head_kernel(float* __restrict__ out, const float* __restrict__ h2,
                 const float* __restrict__ W2, const float* __restrict__ b2)
{
    __shared__ float sW[H2D][NC];
    __shared__ float sh[16][H2D + 4];

    int t = threadIdx.x;
    #pragma unroll
    for (int i = 0; i < 16; i++) {
        int idx = t + i * 256;
        int c = idx >> 8, k = idx & 255;
        sW[k][c] = W2[idx];
    }
    int r0 = blockIdx.x * 16;
    #pragma unroll
    for (int i = 0; i < 4; i++) {
        int vid = t + i * 256;
        int row = vid >> 6;
        int kv  = (vid & 63) << 2;
        *(float4*)&sh[row][kv] = *(const float4*)(h2 + (size_t)(r0 + row) * H2D + kv);
    }
    __syncthreads();

    int row = t >> 4, col = t & 15;
    float s = 0.f;
    #pragma unroll 8
    for (int k = 0; k < H2D; k++)
        s = fmaf(sh[row][k], sW[k][col], s);
    s += b2[col];
    out[(size_t)(r0 + row) * NC + col] = 1.0f / (1.0f + expf(-s));
}

// ---------------------------------------------------------------------------
extern "C" void kernel_launch(void* const* d_in, const int* in_sizes, int n_in,
                              void* d_out, int out_size)
{
    const float* x  = (const float*)d_in[0];
    const float* Wp = (const float*)d_in[1];
    const float* bp = (const float*)d_in[2];
    const float* Ws = (const float*)d_in[3];
    const float* Wn = (const float*)d_in[4];
    const float* bn = (const float*)d_in[5];
    const float* W1 = (const float*)d_in[6];
    const float* b1 = (const float*)d_in[7];
    const float* W2 = (const float*)d_in[8];
    const float* b2 = (const float*)d_in[9];
    const int*  src = (const int*)d_in[10];
    const int*  dst = (const int*)d_in[11];
    float* out = (float*)d_out;

    uint32_t* ybf;  float *pooled, *h, *h2;
    int *deg, *off, *cur, *esrc, *chunk;
    cudaGetSymbolAddress((void**)&ybf,    g_ybf);
    cudaGetSymbolAddress((void**)&pooled, g_pooled);
    cudaGetSymbolAddress((void**)&h,      g_h);
    cudaGetSymbolAddress((void**)&h2,     g_h2);
    cudaGetSymbolAddress((void**)&deg,    g_deg);
    cudaGetSymbolAddress((void**)&off,    g_off);
    cudaGetSymbolAddress((void**)&cur,    g_cur);
    cudaGetSymbolAddress((void**)&esrc,   g_esrc);
    cudaGetSymbolAddress((void**)&chunk,  g_chunk);

    cudaFuncSetAttribute(mma_gemm<1, false, true >, cudaFuncAttributeMaxDynamicSharedMemorySize, GEMM_SMEM_BYTES);
    cudaFuncSetAttribute(mma_gemm<2, true,  false>, cudaFuncAttributeMaxDynamicSharedMemorySize, GEMM_SMEM_BYTES);
    cudaFuncSetAttribute(mma_gemm<2, false, false>, cudaFuncAttributeMaxDynamicSharedMemorySize, GEMM_SMEM_BYTES);

    // --- CSR build (by dst) ---
    zero_kernel<<<64, 256>>>((float4*)deg, NN / 4);
    hist_kernel<<<NE / 1024, 256>>>(deg, dst);
    scan_a<<<256, 256>>>(deg, chunk);
    scan_b<<<1, 256>>>(chunk, off);
    scan_c<<<256, 256>>>(deg, chunk, off, cur);
    scatter_kernel<<<NE / 1024, 256>>>(cur, esrc, src, dst);

    // y = relu(x @ Wp^T + bp), packed bf16  [hoisted per-NODE, 16x fewer FLOPs]
    mma_gemm<1, false, true><<<dim3(1, NN / 128), 256, GEMM_SMEM_BYTES>>>(
        (float*)ybf, x, Wp, nullptr, nullptr, bp, H1D);

    // pooled = segment_max(y[src], dst)  — CSR gather-max, no atomics
    pool_kernel<<<NN * 32 / 256, 256>>>(pooled, (const uint4*)ybf, off, esrc);

    // h = leaky( x @ Ws^T + pooled @ Wn^T + bn )  — fused dual-source GEMM
    mma_gemm<2, true, false><<<dim3(1, NN / 128), 256, GEMM_SMEM_BYTES>>>(
        h, x, Ws, pooled, Wn, bn, H1D);

    // h2 = leaky( h @ W1^T + b1 )
    mma_gemm<2, false, false><<<dim3(2, NN / 128), 256, GEMM_SMEM_BYTES>>>(
        h2, h, W1, nullptr, nullptr, b1, H2D);

    // out = sigmoid( h2 @ W2^T + b2 )
    head_kernel<<<NN / 16, 256>>>(out, h2, W2, b2);
}

// round 12
// speedup vs baseline: 1.9358x; 1.1476x over previous
#include <cuda_runtime.h>
#include <cuda_bf16.h>
#include <cstdint>
#include <cstddef>

#define NN   65536
#define NE   1048576
#define FIN  128
#define H1D  128
#define H2D  256
#define NC   16

// Scratch (device globals — no allocation allowed). All feature tensors bf16x2-packed.
__device__ uint32_t g_xb [(size_t)NN * FIN / 2];   // bf16(x)
__device__ uint32_t g_ybf[(size_t)NN * H1D / 2];   // relu(x@Wp^T+bp)
__device__ uint32_t g_pb [(size_t)NN * H1D / 2];   // segment_max (bf16)
__device__ uint32_t g_hb [(size_t)NN * H1D / 2];   // hidden 1
__device__ uint32_t g_h2b[(size_t)NN * H2D / 2];   // hidden 2
__device__ uint32_t g_wb [40960];                  // bf16 weights: Wp|Ws|Wn|W1
__device__ int      g_deg[NN];
__device__ int      g_off[NN + 1];
__device__ int      g_cur[NN];
__device__ int      g_esrc[NE];
__device__ int      g_chunk[256];

// ---------------------------------------------------------------------------
__global__ void zero_kernel(float4* __restrict__ p, int n4) {
    int i = blockIdx.x * blockDim.x + threadIdx.x;
    int stride = gridDim.x * blockDim.x;
    float4 z = make_float4(0.f, 0.f, 0.f, 0.f);
    for (; i < n4; i += stride) p[i] = z;
}

// fp32 -> packed bf16x2 converters
__global__ void cvt_x_kernel(uint32_t* __restrict__ xb, const float4* __restrict__ x4, int n4) {
    int i = blockIdx.x * blockDim.x + threadIdx.x;
    int stride = gridDim.x * blockDim.x;
    for (; i < n4; i += stride) {
        float4 v = __ldg(x4 + i);
        __nv_bfloat162 lo = __float22bfloat162_rn(make_float2(v.x, v.y));
        __nv_bfloat162 hi = __float22bfloat162_rn(make_float2(v.z, v.w));
        xb[2 * i]     = *(uint32_t*)&lo;
        xb[2 * i + 1] = *(uint32_t*)&hi;
    }
}

// 40960 float2 total: Wp[0,8192) Ws[8192,16384) Wn[16384,24576) W1[24576,40960)
__global__ void cvt_w_kernel(uint32_t* __restrict__ wb,
                             const float2* __restrict__ Wp, const float2* __restrict__ Ws,
                             const float2* __restrict__ Wn, const float2* __restrict__ W1) {
    int i = blockIdx.x * blockDim.x + threadIdx.x;   // < 40960
    float2 v;
    if      (i < 8192)  v = Wp[i];
    else if (i < 16384) v = Ws[i - 8192];
    else if (i < 24576) v = Wn[i - 16384];
    else                v = W1[i - 24576];
    __nv_bfloat162 b = __float22bfloat162_rn(v);
    wb[i] = *(uint32_t*)&b;
}

// ---------------------------------------------------------------------------
__global__ void hist_kernel(int* __restrict__ deg, const int* __restrict__ dst) {
    int i = blockIdx.x * blockDim.x + threadIdx.x;   // < NE/4
    int4 d = __ldg((const int4*)dst + i);
    atomicAdd(&deg[d.x], 1);
    atomicAdd(&deg[d.y], 1);
    atomicAdd(&deg[d.z], 1);
    atomicAdd(&deg[d.w], 1);
}

// --- hierarchical exclusive scan over NN = 256*256 ---
__global__ __launch_bounds__(256)
void scan_a(const int* __restrict__ deg, int* __restrict__ chunk) {
    __shared__ int s[256];
    int t = threadIdx.x, c = blockIdx.x;
    s[t] = deg[c * 256 + t];
    __syncthreads();
    for (int d = 128; d > 0; d >>= 1) {
        if (t < d) s[t] += s[t + d];
        __syncthreads();
    }
    if (t == 0) chunk[c] = s[0];
}

__global__ __launch_bounds__(256)
void scan_b(int* __restrict__ chunk, int* __restrict__ off) {
    __shared__ int s[256];
    int t = threadIdx.x;
    int v = chunk[t];
    s[t] = v;
    __syncthreads();
    for (int d = 1; d < 256; d <<= 1) {
        int u = (t >= d) ? s[t - d] : 0;
        __syncthreads();
        s[t] += u;
        __syncthreads();
    }
    chunk[t] = s[t] - v;
    if (t == 255) off[NN] = s[255];
}

__global__ __launch_bounds__(256)
void scan_c(const int* __restrict__ deg, const int* __restrict__ chunk,
            int* __restrict__ off, int* __restrict__ cur) {
    __shared__ int s[256];
    int t = threadIdx.x, c = blockIdx.x;
    int v = deg[c * 256 + t];
    s[t] = v;
    __syncthreads();
    for (int d = 1; d < 256; d <<= 1) {
        int u = (t >= d) ? s[t - d] : 0;
        __syncthreads();
        s[t] += u;
        __syncthreads();
    }
    int o = chunk[c] + s[t] - v;
    off[c * 256 + t] = o;
    cur[c * 256 + t] = o;
}

__global__ void scatter_kernel(int* __restrict__ cur, int* __restrict__ esrc,
                               const int* __restrict__ src, const int* __restrict__ dst) {
    int i = blockIdx.x * blockDim.x + threadIdx.x;   // < NE/4
    int4 d = __ldg((const int4*)dst + i);
    int4 s = __ldg((const int4*)src + i);
    esrc[atomicAdd(&cur[d.x], 1)] = s.x;
    esrc[atomicAdd(&cur[d.y], 1)] = s.y;
    esrc[atomicAdd(&cur[d.z], 1)] = s.z;
    esrc[atomicAdd(&cur[d.w], 1)] = s.w;
}

// ---------------------------------------------------------------------------
__device__ __forceinline__ uint32_t bmax2(uint32_t a, uint32_t b) {
    __nv_bfloat162 r = __hmax2(*(__nv_bfloat162*)&a, *(__nv_bfloat162*)&b);
    return *(uint32_t*)&r;
}
__device__ __forceinline__ uint4 bmax4(uint4 a, uint4 b) {
    uint4 r;
    r.x = bmax2(a.x, b.x); r.y = bmax2(a.y, b.y);
    r.z = bmax2(a.z, b.z); r.w = bmax2(a.w, b.w);
    return r;
}

// One warp per node: pooled_bf[n] = max over in-edges of y_bf16[src].
// 16 lanes per 256B row (uint4 loads), halves take alternating edges,
// cross-half combine via shfl_xor(16), bf16 output written directly
// (input is bf16 so this is exact). Empty nodes write 0.
__global__ __launch_bounds__(256)
void pool_kernel(uint4* __restrict__ pooled4, const uint4* __restrict__ yb4,
                 const int* __restrict__ off, const int* __restrict__ esrc)
{
    const int n    = (blockIdx.x * blockDim.x + threadIdx.x) >> 5;
    const int lane = threadIdx.x & 31;
    const int half = lane >> 4, sl = lane & 15;
    const int beg = __ldg(off + n), end = __ldg(off + n + 1);

    uint4 a0 = {0u, 0u, 0u, 0u}, a1 = {0u, 0u, 0u, 0u};
    int e = beg;
    #pragma unroll 1
    for (; e + 3 < end; e += 4) {
        int s0 = __ldg(esrc + e + half);
        int s1 = __ldg(esrc + e + 2 + half);
        uint4 v0 = __ldg(yb4 + (size_t)s0 * 16 + sl);
        uint4 v1 = __ldg(yb4 + (size_t)s1 * 16 + sl);
        a0 = bmax4(a0, v0);
        a1 = bmax4(a1, v1);
    }
    if (e + 1 < end) {
        int s0 = __ldg(esrc + e + half);
        a0 = bmax4(a0, __ldg(yb4 + (size_t)s0 * 16 + sl));
        e += 2;
    }
    if (e < end) {
        int s0 = __ldg(esrc + e);
        a0 = bmax4(a0, __ldg(yb4 + (size_t)s0 * 16 + sl));
    }
    a0 = bmax4(a0, a1);
    a0.x = bmax2(a0.x, __shfl_xor_sync(0xFFFFFFFFu, a0.x, 16));
    a0.y = bmax2(a0.y, __shfl_xor_sync(0xFFFFFFFFu, a0.y, 16));
    a0.z = bmax2(a0.z, __shfl_xor_sync(0xFFFFFFFFu, a0.z, 16));
    a0.w = bmax2(a0.w, __shfl_xor_sync(0xFFFFFFFFu, a0.w, 16));
    if (half == 0)
        pooled4[(size_t)n * 16 + sl] = a0;   // 16 lanes cover full 256B row
}

// ---------------------------------------------------------------------------
// ACT: 0 = none, 1 = relu, 2 = leaky(0.01)
template <int ACT>
__device__ __forceinline__ float apply_act(float v) {
    if (ACT == 1) return v > 0.f ? v : 0.f;
    if (ACT == 2) return v > 0.f ? v : 0.01f * v;
    return v;
}

__device__ __forceinline__ void mma16(float* d, const uint32_t* a, const uint32_t* b) {
    asm volatile(
        "mma.sync.aligned.m16n8k16.row.col.f32.bf16.bf16.f32 "
        "{%0,%1,%2,%3}, {%4,%5,%6,%7}, {%8,%9}, {%0,%1,%2,%3};\n"
        : "+f"(d[0]), "+f"(d[1]), "+f"(d[2]), "+f"(d[3])
        : "r"(a[0]), "r"(a[1]), "r"(a[2]), "r"(a[3]), "r"(b[0]), "r"(b[1]));
}

__device__ __forceinline__ void cp16(uint32_t s, const void* g) {
    asm volatile("cp.async.cg.shared.global [%0], [%1], 16;\n" :: "r"(s), "l"(g));
}

// ---------------------------------------------------------------------------
// C_bf16[M,N] = act( A1[M,128] @ B1[N,128]^T  (+ A2 @ B2^T if DUAL)  + bias )
// All operands bf16 (row-major), fp32 accumulate, bf16x2-packed output.
// BM=128, BN=128, BK=64, 2-stage cp.async pipeline, 8 warps (2x4),
// warp tile 64x32, m16n8k16 fragments. Smem row stride 36 u32 -> fragment
// LDS conflict-free: bank = (4g+q+kb)%32 distinct across the warp.
#define GEMM_SMEM_BYTES (4 * 128 * 36 * 4)   // 2 stages x (A+B) x 128x36 u32

template <int ACT, bool DUAL>
__global__ __launch_bounds__(256, 2)
void mma_gemm(uint32_t* __restrict__ C,
              const __nv_bfloat16* __restrict__ A1, const __nv_bfloat16* __restrict__ B1,
              const __nv_bfloat16* __restrict__ A2, const __nv_bfloat16* __restrict__ B2,
              const float* __restrict__ bias, int N)
{
    constexpr int K = 128, BK = 64, LDSU = 36;   // stride in u32 (bf16x2) units
    constexpr int KT = DUAL ? 4 : 2;             // BK-steps total
    constexpr int BUF = 128 * LDSU;

    extern __shared__ uint32_t smem[];
    uint32_t* As[2] = { smem,           smem + BUF     };
    uint32_t* Bs[2] = { smem + 2*BUF,   smem + 3*BUF   };

    const int t    = threadIdx.x;
    const int lane = t & 31, w = t >> 5;
    const int wm = w >> 2, wn = w & 3;
    const int g  = lane >> 2, q = lane & 3;
    const int bm = blockIdx.y * 128, bn = blockIdx.x * 128;

    float acc[4][4][4];
    #pragma unroll
    for (int i = 0; i < 4; i++)
        #pragma unroll
        for (int j = 0; j < 4; j++)
            #pragma unroll
            for (int v = 0; v < 4; v++) acc[i][j][v] = 0.f;

    auto load_stage = [&](int kt, int st) {
        const __nv_bfloat16* Ap = (DUAL && kt >= 2) ? A2 : A1;
        const __nv_bfloat16* Bp = (DUAL && kt >= 2) ? B2 : B1;
        const int k0 = (kt & 1) * BK;            // bf16-element offset
        #pragma unroll
        for (int i = 0; i < 4; i++) {
            int id  = t + i * 256;               // 0..1023
            int row = id >> 3;                   // 0..127
            int kv  = (id & 7);                  // 8 x 16B per row (64 bf16)
            cp16((uint32_t)__cvta_generic_to_shared(&As[st][row * LDSU + kv * 4]),
                 Ap + (size_t)(bm + row) * K + k0 + kv * 8);
            cp16((uint32_t)__cvta_generic_to_shared(&Bs[st][row * LDSU + kv * 4]),
                 Bp + (size_t)(bn + row) * K + k0 + kv * 8);
        }
        asm volatile("cp.async.commit_group;\n");
    };

    load_stage(0, 0);

    #pragma unroll
    for (int kt = 0; kt < KT; kt++) {
        const int st = kt & 1;
        if (kt + 1 < KT) {
            load_stage(kt + 1, st ^ 1);
            asm volatile("cp.async.wait_group 1;\n");
        } else {
            asm volatile("cp.async.wait_group 0;\n");
        }
        __syncthreads();

        const uint32_t* Aw = &As[st][(wm * 64) * LDSU];
        const uint32_t* Bw = &Bs[st][(wn * 32) * LDSU];

        #pragma unroll
        for (int kk = 0; kk < 4; kk++) {         // 4 x k16 per BK=64
            const int kb = kk * 8;               // u32 offset
            uint32_t bf[4][2];
            #pragma unroll
            for (int nj = 0; nj < 4; nj++) {
                bf[nj][0] = Bw[(nj * 8 + g) * LDSU + kb + q];
                bf[nj][1] = Bw[(nj * 8 + g) * LDSU + kb + q + 4];
            }
            #pragma unroll
            for (int mi = 0; mi < 4; mi++) {
                uint32_t af[4];
                af[0] = Aw[(mi * 16 + g    ) * LDSU + kb + q    ];
                af[1] = Aw[(mi * 16 + g + 8) * LDSU + kb + q    ];
                af[2] = Aw[(mi * 16 + g    ) * LDSU + kb + q + 4];
                af[3] = Aw[(mi * 16 + g + 8) * LDSU + kb + q + 4];
                #pragma unroll
                for (int nj = 0; nj < 4; nj++)
                    mma16(acc[mi][nj], af, bf[nj]);
            }
        }
        __syncthreads();
    }

    const int N2 = N >> 1;                       // u32 row stride
    #pragma unroll
    for (int mi = 0; mi < 4; mi++) {
        const int r0 = bm + wm * 64 + mi * 16 + g;
        #pragma unroll
        for (int nj = 0; nj < 4; nj++) {
            const int c = bn + wn * 32 + nj * 8 + q * 2;
            const float bx = bias[c], by = bias[c + 1];
            float2 v0, v1;
            v0.x = apply_act<ACT>(acc[mi][nj][0] + bx);
            v0.y = apply_act<ACT>(acc[mi][nj][1] + by);
            v1.x = apply_act<ACT>(acc[mi][nj][2] + bx);
            v1.y = apply_act<ACT>(acc[mi][nj][3] + by);
            __nv_bfloat162 p0 = __float22bfloat162_rn(v0);
            __nv_bfloat162 p1 = __float22bfloat162_rn(v1);
            C[(size_t)r0 * N2 + (c >> 1)]       = *(uint32_t*)&p0;
            C[(size_t)(r0 + 8) * N2 + (c >> 1)] = *(uint32_t*)&p1;
        }
    }
}

// ---------------------------------------------------------------------------
// out[n, c] = sigmoid( h2[n, :] . W2[c, :] + b2[c] ),  h2 bf16-packed, K=256
__global__ __launch_bounds__(256)
void head_kernel(float* __restrict__ out, const uint32_t* __restrict__ h2b,
                 const float* __restrict__ W2, const float* __restrict__ b2)
{
    __shared__ float sW[H2D][NC];
    __shared__ float sh[16][H2D + 4];

    int t = threadIdx.x;
    #pragma unroll
    for (int i = 0; i < 16; i++) {
        int idx = t + i * 256;
        int c = idx >> 8, k = idx & 255;
        sW[k][c] = W2[idx];
    }
    int r0 = blockIdx.x * 16;
    #pragma unroll
    for (int i = 0; i < 8; i++) {
        int vid = t + i * 256;            // 0..2047 u32 slots (16 rows x 128)
        int row = vid >> 7;
        int cp  = vid & 127;
        uint32_t u = h2b[(size_t)(r0 + row) * 128 + cp];
        float2 f = __bfloat1622float2(*(__nv_bfloat162*)&u);
        sh[row][2 * cp]     = f.x;
        sh[row][2 * cp + 1] = f.y;
    }
    __syncthreads();

    int row = t >> 4, col = t & 15;
    float s = 0.f;
    #pragma unroll 8
    for (int k = 0; k < H2D; k++)
        s = fmaf(sh[row][k], sW[k][col], s);
    s += b2[col];
    out[(size_t)(r0 + row) * NC + col] = 1.0f / (1.0f + expf(-s));
}

// ---------------------------------------------------------------------------
extern "C" void kernel_launch(void* const* d_in, const int* in_sizes, int n_in,
                              void* d_out, int out_size)
{
    const float* x  = (const float*)d_in[0];
    const float* Wp = (const float*)d_in[1];
    const float* bp = (const float*)d_in[2];
    const float* Ws = (const float*)d_in[3];
    const float* Wn = (const float*)d_in[4];
    const float* bn = (const float*)d_in[5];
    const float* W1 = (const float*)d_in[6];
    const float* b1 = (const float*)d_in[7];
    const float* W2 = (const float*)d_in[8];
    const float* b2 = (const float*)d_in[9];
    const int*  src = (const int*)d_in[10];
    const int*  dst = (const int*)d_in[11];
    float* out = (float*)d_out;

    uint32_t *xb, *ybf, *pb, *hb, *h2b, *wb;
    int *deg, *off, *cur, *esrc, *chunk;
    cudaGetSymbolAddress((void**)&xb,    g_xb);
    cudaGetSymbolAddress((void**)&ybf,   g_ybf);
    cudaGetSymbolAddress((void**)&pb,    g_pb);
    cudaGetSymbolAddress((void**)&hb,    g_hb);
    cudaGetSymbolAddress((void**)&h2b,   g_h2b);
    cudaGetSymbolAddress((void**)&wb,    g_wb);
    cudaGetSymbolAddress((void**)&deg,   g_deg);
    cudaGetSymbolAddress((void**)&off,   g_off);
    cudaGetSymbolAddress((void**)&cur,   g_cur);
    cudaGetSymbolAddress((void**)&esrc,  g_esrc);
    cudaGetSymbolAddress((void**)&chunk, g_chunk);

    const __nv_bfloat16* Wpb = (const __nv_bfloat16*)wb;
    const __nv_bfloat16* Wsb = (const __nv_bfloat16*)wb + 16384;
    const __nv_bfloat16* Wnb = (const __nv_bfloat16*)wb + 32768;
    const __nv_bfloat16* W1b = (const __nv_bfloat16*)wb + 49152;

    cudaFuncSetAttribute(mma_gemm<1, false>, cudaFuncAttributeMaxDynamicSharedMemorySize, GEMM_SMEM_BYTES);
    cudaFuncSetAttribute(mma_gemm<2, true >, cudaFuncAttributeMaxDynamicSharedMemorySize, GEMM_SMEM_BYTES);
    cudaFuncSetAttribute(mma_gemm<2, false>, cudaFuncAttributeMaxDynamicSharedMemorySize, GEMM_SMEM_BYTES);

    // --- converts + CSR build ---
    cvt_x_kernel<<<2048, 256>>>(xb, (const float4*)x, NN * FIN / 4);
    cvt_w_kernel<<<160, 256>>>(wb, (const float2*)Wp, (const float2*)Ws,
                               (const float2*)Wn, (const float2*)W1);
    zero_kernel<<<64, 256>>>((float4*)deg, NN / 4);
    hist_kernel<<<NE / 1024, 256>>>(deg, dst);
    scan_a<<<256, 256>>>(deg, chunk);
    scan_b<<<1, 256>>>(chunk, off);
    scan_c<<<256, 256>>>(deg, chunk, off, cur);
    scatter_kernel<<<NE / 1024, 256>>>(cur, esrc, src, dst);

    // y = relu(xb @ Wp^T + bp)  [hoisted per-NODE, 16x fewer FLOPs than per-edge]
    mma_gemm<1, false><<<dim3(1, NN / 128), 256, GEMM_SMEM_BYTES>>>(
        ybf, (const __nv_bfloat16*)xb, Wpb, nullptr, nullptr, bp, H1D);

    // pooled = segment_max(y[src], dst)  — CSR gather-max, bf16 in/out, no atomics
    pool_kernel<<<NN * 32 / 256, 256>>>((uint4*)pb, (const uint4*)ybf, off, esrc);

    // h = leaky( xb @ Ws^T + pooled @ Wn^T + bn )  — fused dual-source GEMM
    mma_gemm<2, true><<<dim3(1, NN / 128), 256, GEMM_SMEM_BYTES>>>(
        hb, (const __nv_bfloat16*)xb, Wsb, (const __nv_bfloat16*)pb, Wnb, bn, H1D);

    // h2 = leaky( h @ W1^T + b1 )
    mma_gemm<2, false><<<dim3(2, NN / 128), 256, GEMM_SMEM_BYTES>>>(
        h2b, (const __nv_bfloat16*)hb, W1b, nullptr, nullptr, b1, H2D);

    // out = sigmoid( h2 @ W2^T + b2 )
    head_kernel<<<NN / 16, 256>>>(out, h2b, W2, b2);
}

// round 13
// speedup vs baseline: 1.9680x; 1.0166x over previous
#include <cuda_runtime.h>
#include <cuda_bf16.h>
#include <cstdint>
#include <cstddef>

#define NN   65536
#define NE   1048576
#define FIN  128
#define H1D  128
#define H2D  256
#define NC   16

// Scratch (device globals — no allocation allowed). All feature tensors bf16x2-packed.
__device__ uint32_t g_xb [(size_t)NN * FIN / 2];   // bf16(x)
__device__ uint32_t g_ybf[(size_t)NN * H1D / 2];   // relu(x@Wp^T+bp)
__device__ uint32_t g_pb [(size_t)NN * H1D / 2];   // segment_max (bf16)
__device__ uint32_t g_hb [(size_t)NN * H1D / 2];   // hidden 1
__device__ uint32_t g_h2b[(size_t)NN * H2D / 2];   // hidden 2
__device__ uint32_t g_wb [40960];                  // bf16 weights: Wp|Ws|Wn|W1
__device__ int      g_deg[NN];
__device__ int      g_off[NN + 1];
__device__ int      g_cur[NN];
__device__ int      g_esrc[NE];
__device__ int      g_chunk[256];

// ---------------------------------------------------------------------------
__global__ void zero_kernel(float4* __restrict__ p, int n4) {
    int i = blockIdx.x * blockDim.x + threadIdx.x;
    int stride = gridDim.x * blockDim.x;
    float4 z = make_float4(0.f, 0.f, 0.f, 0.f);
    for (; i < n4; i += stride) p[i] = z;
}

// fp32 -> packed bf16x2 converters
__global__ void cvt_x_kernel(uint32_t* __restrict__ xb, const float4* __restrict__ x4, int n4) {
    int i = blockIdx.x * blockDim.x + threadIdx.x;
    int stride = gridDim.x * blockDim.x;
    for (; i < n4; i += stride) {
        float4 v = __ldg(x4 + i);
        __nv_bfloat162 lo = __float22bfloat162_rn(make_float2(v.x, v.y));
        __nv_bfloat162 hi = __float22bfloat162_rn(make_float2(v.z, v.w));
        xb[2 * i]     = *(uint32_t*)&lo;
        xb[2 * i + 1] = *(uint32_t*)&hi;
    }
}

// 40960 float2 total: Wp[0,8192) Ws[8192,16384) Wn[16384,24576) W1[24576,40960)
__global__ void cvt_w_kernel(uint32_t* __restrict__ wb,
                             const float2* __restrict__ Wp, const float2* __restrict__ Ws,
                             const float2* __restrict__ Wn, const float2* __restrict__ W1) {
    int i = blockIdx.x * blockDim.x + threadIdx.x;   // < 40960
    float2 v;
    if      (i < 8192)  v = Wp[i];
    else if (i < 16384) v = Ws[i - 8192];
    else if (i < 24576) v = Wn[i - 16384];
    else                v = W1[i - 24576];
    __nv_bfloat162 b = __float22bfloat162_rn(v);
    wb[i] = *(uint32_t*)&b;
}

// ---------------------------------------------------------------------------
// Histogram of dst: 16 edges per thread via 4 upfront int4 loads (MLP=4).
// NE/4 = 262144 int4, 65536 threads.
__global__ void hist_kernel(int* __restrict__ deg, const int4* __restrict__ dst4) {
    int i = blockIdx.x * blockDim.x + threadIdx.x;   // < 65536
    int4 a = __ldg(dst4 + i);
    int4 b = __ldg(dst4 + i + 65536);
    int4 c = __ldg(dst4 + i + 131072);
    int4 d = __ldg(dst4 + i + 196608);
    atomicAdd(&deg[a.x], 1); atomicAdd(&deg[a.y], 1);
    atomicAdd(&deg[a.z], 1); atomicAdd(&deg[a.w], 1);
    atomicAdd(&deg[b.x], 1); atomicAdd(&deg[b.y], 1);
    atomicAdd(&deg[b.z], 1); atomicAdd(&deg[b.w], 1);
    atomicAdd(&deg[c.x], 1); atomicAdd(&deg[c.y], 1);
    atomicAdd(&deg[c.z], 1); atomicAdd(&deg[c.w], 1);
    atomicAdd(&deg[d.x], 1); atomicAdd(&deg[d.y], 1);
    atomicAdd(&deg[d.z], 1); atomicAdd(&deg[d.w], 1);
}

// --- hierarchical exclusive scan over NN = 256*256 ---
__global__ __launch_bounds__(256)
void scan_a(const int* __restrict__ deg, int* __restrict__ chunk) {
    __shared__ int s[256];
    int t = threadIdx.x, c = blockIdx.x;
    s[t] = deg[c * 256 + t];
    __syncthreads();
    for (int d = 128; d > 0; d >>= 1) {
        if (t < d) s[t] += s[t + d];
        __syncthreads();
    }
    if (t == 0) chunk[c] = s[0];
}

__global__ __launch_bounds__(256)
void scan_b(int* __restrict__ chunk, int* __restrict__ off) {
    __shared__ int s[256];
    int t = threadIdx.x;
    int v = chunk[t];
    s[t] = v;
    __syncthreads();
    for (int d = 1; d < 256; d <<= 1) {
        int u = (t >= d) ? s[t - d] : 0;
        __syncthreads();
        s[t] += u;
        __syncthreads();
    }
    chunk[t] = s[t] - v;
    if (t == 255) off[NN] = s[255];
}

__global__ __launch_bounds__(256)
void scan_c(const int* __restrict__ deg, const int* __restrict__ chunk,
            int* __restrict__ off, int* __restrict__ cur) {
    __shared__ int s[256];
    int t = threadIdx.x, c = blockIdx.x;
    int v = deg[c * 256 + t];
    s[t] = v;
    __syncthreads();
    for (int d = 1; d < 256; d <<= 1) {
        int u = (t >= d) ? s[t - d] : 0;
        __syncthreads();
        s[t] += u;
        __syncthreads();
    }
    int o = chunk[c] + s[t] - v;
    off[c * 256 + t] = o;
    cur[c * 256 + t] = o;
}

// Scatter: 16 edges per thread, 8 upfront int4 loads (MLP=8).
__global__ void scatter_kernel(int* __restrict__ cur, int* __restrict__ esrc,
                               const int4* __restrict__ src4, const int4* __restrict__ dst4) {
    int i = blockIdx.x * blockDim.x + threadIdx.x;   // < 65536
    int4 da = __ldg(dst4 + i);
    int4 db = __ldg(dst4 + i + 65536);
    int4 dc = __ldg(dst4 + i + 131072);
    int4 dd = __ldg(dst4 + i + 196608);
    int4 sa = __ldg(src4 + i);
    int4 sb = __ldg(src4 + i + 65536);
    int4 sc = __ldg(src4 + i + 131072);
    int4 sd = __ldg(src4 + i + 196608);
    esrc[atomicAdd(&cur[da.x], 1)] = sa.x;
    esrc[atomicAdd(&cur[da.y], 1)] = sa.y;
    esrc[atomicAdd(&cur[da.z], 1)] = sa.z;
    esrc[atomicAdd(&cur[da.w], 1)] = sa.w;
    esrc[atomicAdd(&cur[db.x], 1)] = sb.x;
    esrc[atomicAdd(&cur[db.y], 1)] = sb.y;
    esrc[atomicAdd(&cur[db.z], 1)] = sb.z;
    esrc[atomicAdd(&cur[db.w], 1)] = sb.w;
    esrc[atomicAdd(&cur[dc.x], 1)] = sc.x;
    esrc[atomicAdd(&cur[dc.y], 1)] = sc.y;
    esrc[atomicAdd(&cur[dc.z], 1)] = sc.z;
    esrc[atomicAdd(&cur[dc.w], 1)] = sc.w;
    esrc[atomicAdd(&cur[dd.x], 1)] = sd.x;
    esrc[atomicAdd(&cur[dd.y], 1)] = sd.y;
    esrc[atomicAdd(&cur[dd.z], 1)] = sd.z;
    esrc[atomicAdd(&cur[dd.w], 1)] = sd.w;
}

// ---------------------------------------------------------------------------
__device__ __forceinline__ uint32_t bmax2(uint32_t a, uint32_t b) {
    __nv_bfloat162 r = __hmax2(*(__nv_bfloat162*)&a, *(__nv_bfloat162*)&b);
    return *(uint32_t*)&r;
}
__device__ __forceinline__ uint4 bmax4(uint4 a, uint4 b) {
    uint4 r;
    r.x = bmax2(a.x, b.x); r.y = bmax2(a.y, b.y);
    r.z = bmax2(a.z, b.z); r.w = bmax2(a.w, b.w);
    return r;
}

// One warp per node: pooled_bf[n] = max over in-edges of y_bf16[src].
// 16 lanes per 256B row (uint4 loads), half-warps take alternating edges,
// 8 edges per iteration -> 4 independent LDG.128 in flight per lane (MLP=4).
// Cross-half combine via shfl_xor(16). Empty nodes write 0.
__global__ __launch_bounds__(256)
void pool_kernel(uint4* __restrict__ pooled4, const uint4* __restrict__ yb4,
                 const int* __restrict__ off, const int* __restrict__ esrc)
{
    const int n    = (blockIdx.x * blockDim.x + threadIdx.x) >> 5;
    const int lane = threadIdx.x & 31;
    const int half = lane >> 4, sl = lane & 15;
    const int beg = __ldg(off + n), end = __ldg(off + n + 1);

    uint4 a0 = {0u,0u,0u,0u}, a1 = {0u,0u,0u,0u};
    uint4 a2 = {0u,0u,0u,0u}, a3 = {0u,0u,0u,0u};
    int e = beg;
    #pragma unroll 1
    for (; e + 7 < end; e += 8) {          // 8 edges: 4 per half-warp
        int s0 = __ldg(esrc + e     + half);
        int s1 = __ldg(esrc + e + 2 + half);
        int s2 = __ldg(esrc + e + 4 + half);
        int s3 = __ldg(esrc + e + 6 + half);
        uint4 v0 = __ldg(yb4 + (size_t)s0 * 16 + sl);
        uint4 v1 = __ldg(yb4 + (size_t)s1 * 16 + sl);
        uint4 v2 = __ldg(yb4 + (size_t)s2 * 16 + sl);
        uint4 v3 = __ldg(yb4 + (size_t)s3 * 16 + sl);
        a0 = bmax4(a0, v0); a1 = bmax4(a1, v1);
        a2 = bmax4(a2, v2); a3 = bmax4(a3, v3);
    }
    if (e + 3 < end) {                     // 4 edges: 2 per half
        int s0 = __ldg(esrc + e     + half);
        int s1 = __ldg(esrc + e + 2 + half);
        uint4 v0 = __ldg(yb4 + (size_t)s0 * 16 + sl);
        uint4 v1 = __ldg(yb4 + (size_t)s1 * 16 + sl);
        a0 = bmax4(a0, v0); a1 = bmax4(a1, v1);
        e += 4;
    }
    if (e + 1 < end) {                     // 2 edges: 1 per half
        int s0 = __ldg(esrc + e + half);
        a0 = bmax4(a0, __ldg(yb4 + (size_t)s0 * 16 + sl));
        e += 2;
    }
    if (e < end) {                         // last edge (both halves load it)
        int s0 = __ldg(esrc + e);
        a0 = bmax4(a0, __ldg(yb4 + (size_t)s0 * 16 + sl));
    }
    a0 = bmax4(bmax4(a0, a1), bmax4(a2, a3));
    a0.x = bmax2(a0.x, __shfl_xor_sync(0xFFFFFFFFu, a0.x, 16));
    a0.y = bmax2(a0.y, __shfl_xor_sync(0xFFFFFFFFu, a0.y, 16));
    a0.z = bmax2(a0.z, __shfl_xor_sync(0xFFFFFFFFu, a0.z, 16));
    a0.w = bmax2(a0.w, __shfl_xor_sync(0xFFFFFFFFu, a0.w, 16));
    if (half == 0)
        pooled4[(size_t)n * 16 + sl] = a0;   // 16 lanes cover full 256B row
}

// ---------------------------------------------------------------------------
// ACT: 0 = none, 1 = relu, 2 = leaky(0.01)
template <int ACT>
__device__ __forceinline__ float apply_act(float v) {
    if (ACT == 1) return v > 0.f ? v : 0.f;
    if (ACT == 2) return v > 0.f ? v : 0.01f * v;
    return v;
}

__device__ __forceinline__ void mma16(float* d, const uint32_t* a, const uint32_t* b) {
    asm volatile(
        "mma.sync.aligned.m16n8k16.row.col.f32.bf16.bf16.f32 "
        "{%0,%1,%2,%3}, {%4,%5,%6,%7}, {%8,%9}, {%0,%1,%2,%3};\n"
        : "+f"(d[0]), "+f"(d[1]), "+f"(d[2]), "+f"(d[3])
        : "r"(a[0]), "r"(a[1]), "r"(a[2]), "r"(a[3]), "r"(b[0]), "r"(b[1]));
}

__device__ __forceinline__ void cp16(uint32_t s, const void* g) {
    asm volatile("cp.async.cg.shared.global [%0], [%1], 16;\n" :: "r"(s), "l"(g));
}

// ---------------------------------------------------------------------------
// C_bf16[M,N] = act( A1[M,128] @ B1[N,128]^T  (+ A2 @ B2^T if DUAL)  + bias )
// All operands bf16 (row-major), fp32 accumulate, bf16x2-packed output.
// BM=128, BN=128, BK=64, 2-stage cp.async pipeline, 8 warps (2x4),
// warp tile 64x32, m16n8k16 fragments. Smem row stride 36 u32.
#define GEMM_SMEM_BYTES (4 * 128 * 36 * 4)

template <int ACT, bool DUAL>
__global__ __launch_bounds__(256, 2)
void mma_gemm(uint32_t* __restrict__ C,
              const __nv_bfloat16* __restrict__ A1, const __nv_bfloat16* __restrict__ B1,
              const __nv_bfloat16* __restrict__ A2, const __nv_bfloat16* __restrict__ B2,
              const float* __restrict__ bias, int N)
{
    constexpr int K = 128, BK = 64, LDSU = 36;
    constexpr int KT = DUAL ? 4 : 2;
    constexpr int BUF = 128 * LDSU;

    extern __shared__ uint32_t smem[];
    uint32_t* As[2] = { smem,           smem + BUF     };
    uint32_t* Bs[2] = { smem + 2*BUF,   smem + 3*BUF   };

    const int t    = threadIdx.x;
    const int lane = t & 31, w = t >> 5;
    const int wm = w >> 2, wn = w & 3;
    const int g  = lane >> 2, q = lane & 3;
    const int bm = blockIdx.y * 128, bn = blockIdx.x * 128;

    float acc[4][4][4];
    #pragma unroll
    for (int i = 0; i < 4; i++)
        #pragma unroll
        for (int j = 0; j < 4; j++)
            #pragma unroll
            for (int v = 0; v < 4; v++) acc[i][j][v] = 0.f;

    auto load_stage = [&](int kt, int st) {
        const __nv_bfloat16* Ap = (DUAL && kt >= 2) ? A2 : A1;
        const __nv_bfloat16* Bp = (DUAL && kt >= 2) ? B2 : B1;
        const int k0 = (kt & 1) * BK;
        #pragma unroll
        for (int i = 0; i < 4; i++) {
            int id  = t + i * 256;
            int row = id >> 3;
            int kv  = (id & 7);
            cp16((uint32_t)__cvta_generic_to_shared(&As[st][row * LDSU + kv * 4]),
                 Ap + (size_t)(bm + row) * K + k0 + kv * 8);
            cp16((uint32_t)__cvta_generic_to_shared(&Bs[st][row * LDSU + kv * 4]),
                 Bp + (size_t)(bn + row) * K + k0 + kv * 8);
        }
        asm volatile("cp.async.commit_group;\n");
    };

    load_stage(0, 0);

    #pragma unroll
    for (int kt = 0; kt < KT; kt++) {
        const int st = kt & 1;
        if (kt + 1 < KT) {
            load_stage(kt + 1, st ^ 1);
            asm volatile("cp.async.wait_group 1;\n");
        } else {
            asm volatile("cp.async.wait_group 0;\n");
        }
        __syncthreads();

        const uint32_t* Aw = &As[st][(wm * 64) * LDSU];
        const uint32_t* Bw = &Bs[st][(wn * 32) * LDSU];

        #pragma unroll
        for (int kk = 0; kk < 4; kk++) {
            const int kb = kk * 8;
            uint32_t bf[4][2];
            #pragma unroll
            for (int nj = 0; nj < 4; nj++) {
                bf[nj][0] = Bw[(nj * 8 + g) * LDSU + kb + q];
                bf[nj][1] = Bw[(nj * 8 + g) * LDSU + kb + q + 4];
            }
            #pragma unroll
            for (int mi = 0; mi < 4; mi++) {
                uint32_t af[4];
                af[0] = Aw[(mi * 16 + g    ) * LDSU + kb + q    ];
                af[1] = Aw[(mi * 16 + g + 8) * LDSU + kb + q    ];
                af[2] = Aw[(mi * 16 + g    ) * LDSU + kb + q + 4];
                af[3] = Aw[(mi * 16 + g + 8) * LDSU + kb + q + 4];
                #pragma unroll
                for (int nj = 0; nj < 4; nj++)
                    mma16(acc[mi][nj], af, bf[nj]);
            }
        }
        __syncthreads();
    }

    const int N2 = N >> 1;
    #pragma unroll
    for (int mi = 0; mi < 4; mi++) {
        const int r0 = bm + wm * 64 + mi * 16 + g;
        #pragma unroll
        for (int nj = 0; nj < 4; nj++) {
            const int c = bn + wn * 32 + nj * 8 + q * 2;
            const float bx = bias[c], by = bias[c + 1];
            float2 v0, v1;
            v0.x = apply_act<ACT>(acc[mi][nj][0] + bx);
            v0.y = apply_act<ACT>(acc[mi][nj][1] + by);
            v1.x = apply_act<ACT>(acc[mi][nj][2] + bx);
            v1.y = apply_act<ACT>(acc[mi][nj][3] + by);
            __nv_bfloat162 p0 = __float22bfloat162_rn(v0);
            __nv_bfloat162 p1 = __float22bfloat162_rn(v1);
            C[(size_t)r0 * N2 + (c >> 1)]       = *(uint32_t*)&p0;
            C[(size_t)(r0 + 8) * N2 + (c >> 1)] = *(uint32_t*)&p1;
        }
    }
}

// ---------------------------------------------------------------------------
// out[n, c] = sigmoid( h2[n, :] . W2[c, :] + b2[c] ),  h2 bf16-packed, K=256
__global__ __launch_bounds__(256)
void head_kernel(float* __restrict__ out, const uint32_t* __restrict__ h2b,
                 const float* __restrict__ W2, const float* __restrict__ b2)
{
    __shared__ float sW[H2D][NC];
    __shared__ float sh[16][H2D + 4];

    int t = threadIdx.x;
    #pragma unroll
    for (int i = 0; i < 16; i++) {
        int idx = t + i * 256;
        int c = idx >> 8, k = idx & 255;
        sW[k][c] = W2[idx];
    }
    int r0 = blockIdx.x * 16;
    #pragma unroll
    for (int i = 0; i < 8; i++) {
        int vid = t + i * 256;
        int row = vid >> 7;
        int cp  = vid & 127;
        uint32_t u = h2b[(size_t)(r0 + row) * 128 + cp];
        float2 f = __bfloat1622float2(*(__nv_bfloat162*)&u);
        sh[row][2 * cp]     = f.x;
        sh[row][2 * cp + 1] = f.y;
    }
    __syncthreads();

    int row = t >> 4, col = t & 15;
    float s = 0.f;
    #pragma unroll 8
    for (int k = 0; k < H2D; k++)
        s = fmaf(sh[row][k], sW[k][col], s);
    s += b2[col];
    out[(size_t)(r0 + row) * NC + col] = 1.0f / (1.0f + expf(-s));
}

// ---------------------------------------------------------------------------
extern "C" void kernel_launch(void* const* d_in, const int* in_sizes, int n_in,
                              void* d_out, int out_size)
{
    const float* x  = (const float*)d_in[0];
    const float* Wp = (const float*)d_in[1];
    const float* bp = (const float*)d_in[2];
    const float* Ws = (const float*)d_in[3];
    const float* Wn = (const float*)d_in[4];
    const float* bn = (const float*)d_in[5];
    const float* W1 = (const float*)d_in[6];
    const float* b1 = (const float*)d_in[7];
    const float* W2 = (const float*)d_in[8];
    const float* b2 = (const float*)d_in[9];
    const int*  src = (const int*)d_in[10];
    const int*  dst = (const int*)d_in[11];
    float* out = (float*)d_out;

    uint32_t *xb, *ybf, *pb, *hb, *h2b, *wb;
    int *deg, *off, *cur, *esrc, *chunk;
    cudaGetSymbolAddress((void**)&xb,    g_xb);
    cudaGetSymbolAddress((void**)&ybf,   g_ybf);
    cudaGetSymbolAddress((void**)&pb,    g_pb);
    cudaGetSymbolAddress((void**)&hb,    g_hb);
    cudaGetSymbolAddress((void**)&h2b,   g_h2b);
    cudaGetSymbolAddress((void**)&wb,    g_wb);
    cudaGetSymbolAddress((void**)&deg,   g_deg);
    cudaGetSymbolAddress((void**)&off,   g_off);
    cudaGetSymbolAddress((void**)&cur,   g_cur);
    cudaGetSymbolAddress((void**)&esrc,  g_esrc);
    cudaGetSymbolAddress((void**)&chunk, g_chunk);

    const __nv_bfloat16* Wpb = (const __nv_bfloat16*)wb;
    const __nv_bfloat16* Wsb = (const __nv_bfloat16*)wb + 16384;
    const __nv_bfloat16* Wnb = (const __nv_bfloat16*)wb + 32768;
    const __nv_bfloat16* W1b = (const __nv_bfloat16*)wb + 49152;

    cudaFuncSetAttribute(mma_gemm<1, false>, cudaFuncAttributeMaxDynamicSharedMemorySize, GEMM_SMEM_BYTES);
    cudaFuncSetAttribute(mma_gemm<2, true >, cudaFuncAttributeMaxDynamicSharedMemorySize, GEMM_SMEM_BYTES);
    cudaFuncSetAttribute(mma_gemm<2, false>, cudaFuncAttributeMaxDynamicSharedMemorySize, GEMM_SMEM_BYTES);

    // Fork-join: CSR build (stream s2) runs concurrently with cvt+GEMM1 (null
    // stream); join before pool, which needs both esrc and ybf. Stream/events
    // are created once (not device memory; allowed) and are capture-legal
    // fork-join primitives.
    static cudaStream_t s2 = nullptr;
    static cudaEvent_t evFork = nullptr, evJoin = nullptr;
    if (!s2) {
        cudaStreamCreateWithFlags(&s2, cudaStreamNonBlocking);
        cudaEventCreateWithFlags(&evFork, cudaEventDisableTiming);
        cudaEventCreateWithFlags(&evJoin, cudaEventDisableTiming);
    }

    cudaEventRecord(evFork, 0);
    cudaStreamWaitEvent(s2, evFork, 0);

    // --- CSR build (stream s2) ---
    zero_kernel<<<64, 256, 0, s2>>>((float4*)deg, NN / 4);
    hist_kernel<<<256, 256, 0, s2>>>(deg, (const int4*)dst);
    scan_a<<<256, 256, 0, s2>>>(deg, chunk);
    scan_b<<<1, 256, 0, s2>>>(chunk, off);
    scan_c<<<256, 256, 0, s2>>>(deg, chunk, off, cur);
    scatter_kernel<<<256, 256, 0, s2>>>(cur, esrc, (const int4*)src, (const int4*)dst);
    cudaEventRecord(evJoin, s2);

    // --- converts + GEMM1 (null stream, concurrent with CSR build) ---
    cvt_x_kernel<<<2048, 256>>>(xb, (const float4*)x, NN * FIN / 4);
    cvt_w_kernel<<<160, 256>>>(wb, (const float2*)Wp, (const float2*)Ws,
                               (const float2*)Wn, (const float2*)W1);
    // y = relu(xb @ Wp^T + bp)  [hoisted per-NODE, 16x fewer FLOPs than per-edge]
    mma_gemm<1, false><<<dim3(1, NN / 128), 256, GEMM_SMEM_BYTES>>>(
        ybf, (const __nv_bfloat16*)xb, Wpb, nullptr, nullptr, bp, H1D);

    cudaStreamWaitEvent(0, evJoin, 0);

    // pooled = segment_max(y[src], dst)  — CSR gather-max, bf16 in/out, no atomics
    pool_kernel<<<NN * 32 / 256, 256>>>((uint4*)pb, (const uint4*)ybf, off, esrc);

    // h = leaky( xb @ Ws^T + pooled @ Wn^T + bn )  — fused dual-source GEMM
    mma_gemm<2, true><<<dim3(1, NN / 128), 256, GEMM_SMEM_BYTES>>>(
        hb, (const __nv_bfloat16*)xb, Wsb, (const __nv_bfloat16*)pb, Wnb, bn, H1D);

    // h2 = leaky( h @ W1^T + b1 )
    mma_gemm<2, false><<<dim3(2, NN / 128), 256, GEMM_SMEM_BYTES>>>(
        h2b, (const __nv_bfloat16*)hb, W1b, nullptr, nullptr, b1, H2D);

    // out = sigmoid( h2 @ W2^T + b2 )
    head_kernel<<<NN / 16, 256>>>(out, h2b, W2, b2);
}